// round 6
// baseline (speedup 1.0000x reference)
#include <cuda_runtime.h>
#include <cuda_bf16.h>
#include <cstddef>

// ---------------------------------------------------------------------------
// PairClassifier: fused fp32 baseline
//   batch_p / batch_h are INT32 (JAX x64 disabled -> .astype(int64) is a no-op)
//   1. Q = ctx_h@Wq+bq  (columns permuted -> head-contiguous)
//   2. K = ctx_p@Wk+bk  (permuted)
//   3. V = lhs_p@Wv+bv  (already head-contiguous after reshape)
//   4. flash-style masked softmax attention -> att[4096,768]
//   5. h1 = gelu(concat(ctx_h, lhs_h-att) @ W1 + b1)
//   6. h2 = h1@W2 ; LayerNorm(128) ; atomic segment-sum pool
//   7. out = (pooled/count) @ Wc + bc
// ---------------------------------------------------------------------------

#define NPNT 4096
#define NHNT 4096
#define DDIM 512
#define BERT 768
#define HEADS 4
#define NB 32

// scratch (device globals; no allocation allowed)
__device__ float g_Qt[NHNT * DDIM];
__device__ float g_Kt[NPNT * DDIM];
__device__ float g_V [NPNT * BERT];
__device__ float g_att[NHNT * BERT];
__device__ float g_h1[NHNT * 256];
__device__ float g_pooled[NB * 128];
__device__ float g_cnt[NB];

// ---------------------------------------------------------------------------
// zero accumulators (graph replays reuse globals -> must re-zero every launch)
// ---------------------------------------------------------------------------
__global__ void zero_pool_kernel() {
    int i = blockIdx.x * blockDim.x + threadIdx.x;
    if (i < NB * 128) g_pooled[i] = 0.f;
    if (i < NB)       g_cnt[i]    = 0.f;
}

// ---------------------------------------------------------------------------
// SGEMM dest[M,N] = A[M,K] @ W[K,N] + bias, optional Q/K head-permute.
// Destination device-global selected by DST template arg (0=Qt,1=Kt,2=V).
// 128x64 tile, BK=16, 256 threads, 8x4 microtile.
// ---------------------------------------------------------------------------
#define GM_TM 128
#define GM_TN 64
#define GM_TK 16

template<int DST, bool PERM>
__global__ __launch_bounds__(256)
void gemm_bias_kernel(const float* __restrict__ A, const float* __restrict__ W,
                      const float* __restrict__ bias, int M, int N, int K) {
    float* C = (DST == 0) ? g_Qt : (DST == 1) ? g_Kt : g_V;
    __shared__ float As[GM_TK][GM_TM + 1];
    __shared__ float Bs[GM_TK][GM_TN];
    int tid = threadIdx.x;
    int m0 = blockIdx.y * GM_TM, n0 = blockIdx.x * GM_TN;
    int tx = tid & 15, ty = tid >> 4;
    float acc[8][4];
    #pragma unroll
    for (int i = 0; i < 8; i++)
        #pragma unroll
        for (int j = 0; j < 4; j++) acc[i][j] = 0.f;

    for (int k0 = 0; k0 < K; k0 += GM_TK) {
        #pragma unroll
        for (int i = 0; i < 8; i++) {
            int idx = tid + i * 256;
            int m = idx >> 4, k = idx & 15;
            As[k][m] = A[(size_t)(m0 + m) * K + (k0 + k)];
        }
        #pragma unroll
        for (int i = 0; i < 4; i++) {
            int idx = tid + i * 256;
            int k = idx >> 6, n = idx & 63;
            Bs[k][n] = W[(size_t)(k0 + k) * N + (n0 + n)];
        }
        __syncthreads();
        #pragma unroll
        for (int k = 0; k < GM_TK; k++) {
            float a[8], b[4];
            #pragma unroll
            for (int i = 0; i < 8; i++) a[i] = As[k][ty * 8 + i];
            #pragma unroll
            for (int j = 0; j < 4; j++) b[j] = Bs[k][tx * 4 + j];
            #pragma unroll
            for (int i = 0; i < 8; i++)
                #pragma unroll
                for (int j = 0; j < 4; j++) acc[i][j] += a[i] * b[j];
        }
        __syncthreads();
    }
    #pragma unroll
    for (int i = 0; i < 8; i++) {
        int m = m0 + ty * 8 + i;
        #pragma unroll
        for (int j = 0; j < 4; j++) {
            int n = n0 + tx * 4 + j;
            float v = acc[i][j] + bias[n];
            // torch .view(-1,128,4): col c=(d*4+h) -> head-contiguous h*128+d
            int nc = PERM ? ((n & 3) * 128 + (n >> 2)) : n;
            C[(size_t)m * N + nc] = v;
        }
    }
}

// ---------------------------------------------------------------------------
// Fused masked-softmax attention.  grid = (NH/32, HEADS), 256 threads.
// n-tile = 32 query rows, m-tile = 16 key/value rows (static smem < 48KB).
// e = mask ? 0 : exp(s*scale)  (bounded logits -> no running max needed),
// O += P @ V_tile ; denom += rowsum(P).  Final: att = O / denom.
// ---------------------------------------------------------------------------
#define MT 16

__global__ __launch_bounds__(256, 2)
void attn_kernel(const int* __restrict__ batch_p,
                 const int* __restrict__ batch_h) {
    __shared__ float Qs[32 * 128];       // 16 KB
    __shared__ float Ks[MT * 132];       // 8.4 KB (pad keeps float4 align, spreads banks)
    __shared__ float Vs[MT * 192];       // 12 KB
    __shared__ float Ps[32 * MT];        // 2 KB
    __shared__ float denom[32];
    __shared__ int   bpS[MT];

    const int h  = blockIdx.y;
    const int n0 = blockIdx.x * 32;
    const int tid  = threadIdx.x;
    const int lane = tid & 31;
    const int w    = tid >> 5;           // warp 0..7

    // Q tile (resident whole kernel)
    for (int idx = tid; idx < 32 * 128; idx += 256) {
        int i = idx >> 7, d = idx & 127;
        Qs[i * 128 + d] = g_Qt[(size_t)(n0 + i) * DDIM + h * 128 + d];
    }
    if (tid < 32) denom[tid] = 0.f;

    // stage-1 mapping: j = tid&15 (key col), rows i0 and i0+16 (i0 = tid>>4)
    const int j  = tid & 15;
    const int i0 = tid >> 4;
    const int bh0 = batch_h[n0 + i0];
    const int bh1 = batch_h[n0 + i0 + 16];
    __syncthreads();

    // stage-2 accumulators: warp w owns rows 4w..4w+3, cols lane+32u (u<6)
    float acc[4][6];
    #pragma unroll
    for (int r = 0; r < 4; r++)
        #pragma unroll
        for (int u = 0; u < 6; u++) acc[r][u] = 0.f;

    const float scale = 0.08838834764831845f;  // 1/sqrt(128)

    for (int m0 = 0; m0 < NPNT; m0 += MT) {
        for (int idx = tid; idx < MT * 128; idx += 256) {
            int jj = idx >> 7, d = idx & 127;
            Ks[jj * 132 + d] = g_Kt[(size_t)(m0 + jj) * DDIM + h * 128 + d];
        }
        for (int idx = tid; idx < MT * 192; idx += 256) {
            int jj = idx / 192, e = idx % 192;
            Vs[jj * 192 + e] = g_V[(size_t)(m0 + jj) * BERT + h * 192 + e];
        }
        if (tid < MT) bpS[tid] = batch_p[m0 + tid];
        __syncthreads();

        // ---- stage 1: S = Q K^T (32x16), mask, exp ------------------------
        {
            const float4* K4 = (const float4*)(Ks + j * 132);
            const float4* Q0 = (const float4*)(Qs + i0 * 128);
            const float4* Q1 = (const float4*)(Qs + (i0 + 16) * 128);
            float s0 = 0.f, s1 = 0.f;
            #pragma unroll
            for (int d4 = 0; d4 < 32; d4++) {
                float4 kv = K4[d4];
                float4 q0 = Q0[d4];
                float4 q1 = Q1[d4];
                s0 += q0.x * kv.x + q0.y * kv.y + q0.z * kv.z + q0.w * kv.w;
                s1 += q1.x * kv.x + q1.y * kv.y + q1.z * kv.z + q1.w * kv.w;
            }
            const int bp = bpS[j];
            Ps[i0 * MT + j]        = (bh0 == bp) ? 0.f : __expf(s0 * scale);
            Ps[(i0 + 16) * MT + j] = (bh1 == bp) ? 0.f : __expf(s1 * scale);
        }
        __syncthreads();

        // ---- rowsum (tid<32, one row each) + stage 2: O += P @ V ----------
        if (tid < 32) {
            float t = 0.f;
            #pragma unroll
            for (int m = 0; m < MT; m++) t += Ps[tid * MT + m];
            denom[tid] += t;
        }
        #pragma unroll
        for (int m = 0; m < MT; m++) {
            float p0 = Ps[(4 * w + 0) * MT + m];
            float p1 = Ps[(4 * w + 1) * MT + m];
            float p2 = Ps[(4 * w + 2) * MT + m];
            float p3 = Ps[(4 * w + 3) * MT + m];
            #pragma unroll
            for (int u = 0; u < 6; u++) {
                float v = Vs[m * 192 + lane + 32 * u];
                acc[0][u] += p0 * v;
                acc[1][u] += p1 * v;
                acc[2][u] += p2 * v;
                acc[3][u] += p3 * v;
            }
        }
        __syncthreads();
    }

    #pragma unroll
    for (int r = 0; r < 4; r++) {
        int i = 4 * w + r;
        float inv = 1.0f / denom[i];     // never 0: no batch spans all premises
        #pragma unroll
        for (int u = 0; u < 6; u++) {
            g_att[(size_t)(n0 + i) * BERT + h * 192 + lane + 32 * u] = acc[r][u] * inv;
        }
    }
}

// ---------------------------------------------------------------------------
// h1 = gelu(concat(ctx_h, lhs_h - att) @ W1 + b1)   M=4096 K=1280 N=256
// ---------------------------------------------------------------------------
__global__ __launch_bounds__(256)
void gemm_feats_kernel(const float* __restrict__ ctx_h, const float* __restrict__ lhs_h,
                       const float* __restrict__ W1, const float* __restrict__ b1) {
    const int N = 256, K = DDIM + BERT;
    __shared__ float As[GM_TK][GM_TM + 1];
    __shared__ float Bs[GM_TK][GM_TN];
    int tid = threadIdx.x;
    int m0 = blockIdx.y * GM_TM, n0 = blockIdx.x * GM_TN;
    int tx = tid & 15, ty = tid >> 4;
    float acc[8][4];
    #pragma unroll
    for (int i = 0; i < 8; i++)
        #pragma unroll
        for (int j = 0; j < 4; j++) acc[i][j] = 0.f;

    for (int k0 = 0; k0 < K; k0 += GM_TK) {
        #pragma unroll
        for (int i = 0; i < 8; i++) {
            int idx = tid + i * 256;
            int m = idx >> 4, k = idx & 15;
            int gm = m0 + m, gk = k0 + k;
            float a;
            if (gk < DDIM) a = ctx_h[(size_t)gm * DDIM + gk];
            else {
                int kk = gk - DDIM;
                a = lhs_h[(size_t)gm * BERT + kk] - g_att[(size_t)gm * BERT + kk];
            }
            As[k][m] = a;
        }
        #pragma unroll
        for (int i = 0; i < 4; i++) {
            int idx = tid + i * 256;
            int k = idx >> 6, n = idx & 63;
            Bs[k][n] = W1[(size_t)(k0 + k) * N + (n0 + n)];
        }
        __syncthreads();
        #pragma unroll
        for (int k = 0; k < GM_TK; k++) {
            float a[8], b[4];
            #pragma unroll
            for (int i = 0; i < 8; i++) a[i] = As[k][ty * 8 + i];
            #pragma unroll
            for (int j = 0; j < 4; j++) b[j] = Bs[k][tx * 4 + j];
            #pragma unroll
            for (int i = 0; i < 8; i++)
                #pragma unroll
                for (int j = 0; j < 4; j++) acc[i][j] += a[i] * b[j];
        }
        __syncthreads();
    }
    #pragma unroll
    for (int i = 0; i < 8; i++) {
        int m = m0 + ty * 8 + i;
        #pragma unroll
        for (int j = 0; j < 4; j++) {
            int n = n0 + tx * 4 + j;
            float x = acc[i][j] + b1[n];
            g_h1[(size_t)m * 256 + n] = x * normcdff(x);   // exact gelu
        }
    }
}

// ---------------------------------------------------------------------------
// h2 = h1@W2 ; LayerNorm(128) ; atomic pool.  One block per node, 128 thr.
// ---------------------------------------------------------------------------
__global__ __launch_bounds__(128)
void h2_ln_pool_kernel(const float* __restrict__ W2, const float* __restrict__ ln_g,
                       const float* __restrict__ ln_b, const int* __restrict__ batch_h) {
    int n = blockIdx.x;
    int c = threadIdx.x;
    __shared__ float h1s[256];
    __shared__ float red[4];
    h1s[c]       = g_h1[n * 256 + c];
    h1s[c + 128] = g_h1[n * 256 + 128 + c];
    __syncthreads();
    float acc = 0.f;
    #pragma unroll 8
    for (int k = 0; k < 256; k++) acc += h1s[k] * W2[k * 128 + c];

    float s = acc;
    #pragma unroll
    for (int o = 16; o > 0; o >>= 1) s += __shfl_xor_sync(0xffffffffu, s, o);
    if ((c & 31) == 0) red[c >> 5] = s;
    __syncthreads();
    float mu = (red[0] + red[1] + red[2] + red[3]) * (1.f / 128.f);
    __syncthreads();
    float d = acc - mu;
    float v = d * d;
    #pragma unroll
    for (int o = 16; o > 0; o >>= 1) v += __shfl_xor_sync(0xffffffffu, v, o);
    if ((c & 31) == 0) red[c >> 5] = v;
    __syncthreads();
    float var = (red[0] + red[1] + red[2] + red[3]) * (1.f / 128.f);
    float y = d * rsqrtf(var + 1e-5f) * ln_g[c] + ln_b[c];
    int b = batch_h[n];
    atomicAdd(&g_pooled[b * 128 + c], y);
    if (c == 0) atomicAdd(&g_cnt[b], 1.0f);
}

// ---------------------------------------------------------------------------
// out[b,c] = (pooled[b]/max(cnt,1)) @ Wc + bc.  One block, 96 threads.
// ---------------------------------------------------------------------------
__global__ void final_kernel(const float* __restrict__ Wc, const float* __restrict__ bc,
                             float* __restrict__ out) {
    int t = threadIdx.x;
    if (t < NB * 3) {
        int b = t / 3, c = t % 3;
        float inv = 1.0f / fmaxf(g_cnt[b], 1.0f);
        float acc = 0.f;
        #pragma unroll 4
        for (int k = 0; k < 128; k++) acc += g_pooled[b * 128 + k] * Wc[k * 3 + c];
        out[b * 3 + c] = acc * inv + bc[c];
    }
}

// ---------------------------------------------------------------------------
extern "C" void kernel_launch(void* const* d_in, const int* in_sizes, int n_in,
                              void* d_out, int out_size) {
    const float* ctx_p   = (const float*)d_in[0];
    const float* ctx_h   = (const float*)d_in[1];
    const float* lhs_p   = (const float*)d_in[2];
    const float* lhs_h   = (const float*)d_in[3];
    const int*   batch_p = (const int*)d_in[4];   // int32 (JAX x64 disabled)
    const int*   batch_h = (const int*)d_in[5];
    const float* Wq = (const float*)d_in[6];
    const float* bq = (const float*)d_in[7];
    const float* Wk = (const float*)d_in[8];
    const float* bk = (const float*)d_in[9];
    const float* Wv = (const float*)d_in[10];
    const float* bv = (const float*)d_in[11];
    const float* W1 = (const float*)d_in[12];
    const float* b1 = (const float*)d_in[13];
    const float* W2 = (const float*)d_in[14];
    const float* ln_g = (const float*)d_in[15];
    const float* ln_b = (const float*)d_in[16];
    const float* Wc = (const float*)d_in[17];
    const float* bc = (const float*)d_in[18];
    float* out = (float*)d_out;

    zero_pool_kernel<<<16, 256>>>();

    // Q = ctx_h@Wq+bq (permuted), K = ctx_p@Wk+bk (permuted), V = lhs_p@Wv+bv
    gemm_bias_kernel<0, true ><<<dim3(DDIM / GM_TN, NHNT / GM_TM), 256>>>(
        ctx_h, Wq, bq, NHNT, DDIM, DDIM);
    gemm_bias_kernel<1, true ><<<dim3(DDIM / GM_TN, NPNT / GM_TM), 256>>>(
        ctx_p, Wk, bk, NPNT, DDIM, DDIM);
    gemm_bias_kernel<2, false><<<dim3(BERT / GM_TN, NPNT / GM_TM), 256>>>(
        lhs_p, Wv, bv, NPNT, BERT, BERT);

    attn_kernel<<<dim3(NHNT / 32, HEADS), 256>>>(batch_p, batch_h);

    gemm_feats_kernel<<<dim3(256 / GM_TN, NHNT / GM_TM), 256>>>(ctx_h, lhs_h, W1, b1);

    h2_ln_pool_kernel<<<NHNT, 128>>>(W2, ln_g, ln_b, batch_h);

    final_kernel<<<1, 96>>>(Wc, bc, out);
}

// round 12
// speedup vs baseline: 2.8710x; 2.8710x over previous
#include <cuda_runtime.h>
#include <cuda_bf16.h>
#include <cstdint>
#include <cstddef>

// ---------------------------------------------------------------------------
// PairClassifier — Round 7: bf16 mma.sync attention
//   batch arrays are INT32. Projections fp32-compute -> bf16 store.
//   Attention: HMMA m16n8k16 bf16, fp32 accum, unnormalized-exp softmax.
// ---------------------------------------------------------------------------

#define NPNT 4096
#define NHNT 4096
#define DDIM 512
#define BERT 768
#define HEADS 4
#define NB 32

__device__ __nv_bfloat16 g_Qbf[NHNT * DDIM];
__device__ __nv_bfloat16 g_Kbf[NPNT * DDIM];
__device__ __nv_bfloat16 g_Vbf[NPNT * BERT];
__device__ float g_att[NHNT * BERT];
__device__ float g_h1[NHNT * 256];
__device__ float g_pooled[NB * 128];
__device__ float g_cnt[NB];

__global__ void zero_pool_kernel() {
    int i = blockIdx.x * blockDim.x + threadIdx.x;
    if (i < NB * 128) g_pooled[i] = 0.f;
    if (i < NB)       g_cnt[i]    = 0.f;
}

// ---------------------------------------------------------------------------
// SGEMM (fp32 compute) -> bf16 output, optional head-permute epilogue.
// ---------------------------------------------------------------------------
#define GM_TM 128
#define GM_TN 64
#define GM_TK 16

template<int DST, bool PERM>
__global__ __launch_bounds__(256)
void gemm_bias_kernel(const float* __restrict__ A, const float* __restrict__ W,
                      const float* __restrict__ bias, int M, int N, int K) {
    __nv_bfloat16* C = (DST == 0) ? g_Qbf : (DST == 1) ? g_Kbf : g_Vbf;
    __shared__ float As[GM_TK][GM_TM + 1];
    __shared__ float Bs[GM_TK][GM_TN];
    int tid = threadIdx.x;
    int m0 = blockIdx.y * GM_TM, n0 = blockIdx.x * GM_TN;
    int tx = tid & 15, ty = tid >> 4;
    float acc[8][4];
    #pragma unroll
    for (int i = 0; i < 8; i++)
        #pragma unroll
        for (int j = 0; j < 4; j++) acc[i][j] = 0.f;

    for (int k0 = 0; k0 < K; k0 += GM_TK) {
        #pragma unroll
        for (int i = 0; i < 8; i++) {
            int idx = tid + i * 256;
            int m = idx >> 4, k = idx & 15;
            As[k][m] = A[(size_t)(m0 + m) * K + (k0 + k)];
        }
        #pragma unroll
        for (int i = 0; i < 4; i++) {
            int idx = tid + i * 256;
            int k = idx >> 6, n = idx & 63;
            Bs[k][n] = W[(size_t)(k0 + k) * N + (n0 + n)];
        }
        __syncthreads();
        #pragma unroll
        for (int k = 0; k < GM_TK; k++) {
            float a[8], b[4];
            #pragma unroll
            for (int i = 0; i < 8; i++) a[i] = As[k][ty * 8 + i];
            #pragma unroll
            for (int j = 0; j < 4; j++) b[j] = Bs[k][tx * 4 + j];
            #pragma unroll
            for (int i = 0; i < 8; i++)
                #pragma unroll
                for (int j = 0; j < 4; j++) acc[i][j] += a[i] * b[j];
        }
        __syncthreads();
    }
    #pragma unroll
    for (int i = 0; i < 8; i++) {
        int m = m0 + ty * 8 + i;
        #pragma unroll
        for (int j = 0; j < 4; j++) {
            int n = n0 + tx * 4 + j;
            float v = acc[i][j] + bias[n];
            int nc = PERM ? ((n & 3) * 128 + (n >> 2)) : n;   // head-contiguous
            C[(size_t)m * N + nc] = __float2bfloat16(v);
        }
    }
}

// ---------------------------------------------------------------------------
// bf16 tensor-core attention.  grid = (NH/64, HEADS), 256 threads (8 warps).
// Warp w: r = w&3 -> 16 q-rows; c = w>>2 -> stage1 16-col half / stage2 96-col half.
// ---------------------------------------------------------------------------
#define QT 64
#define KT 32

static __device__ __forceinline__ uint32_t packbf(float lo, float hi) {
    unsigned short ul = __bfloat16_as_ushort(__float2bfloat16(lo));
    unsigned short uh = __bfloat16_as_ushort(__float2bfloat16(hi));
    return (uint32_t)ul | ((uint32_t)uh << 16);
}

static __device__ __forceinline__ void mma16816(
    float& c0, float& c1, float& c2, float& c3,
    uint32_t a0, uint32_t a1, uint32_t a2, uint32_t a3,
    uint32_t b0, uint32_t b1) {
    asm volatile(
        "mma.sync.aligned.m16n8k16.row.col.f32.bf16.bf16.f32 "
        "{%0,%1,%2,%3}, {%4,%5,%6,%7}, {%8,%9}, {%0,%1,%2,%3};"
        : "+f"(c0), "+f"(c1), "+f"(c2), "+f"(c3)
        : "r"(a0), "r"(a1), "r"(a2), "r"(a3), "r"(b0), "r"(b1));
}

__global__ __launch_bounds__(256, 2)
void attn_mma_kernel(const int* __restrict__ batch_p,
                     const int* __restrict__ batch_h) {
    __shared__ __align__(16) __nv_bfloat16 Qs[QT * 136];   // 17408 B
    __shared__ __align__(16) __nv_bfloat16 Ks[KT * 136];   //  8704 B
    __shared__ __align__(16) __nv_bfloat16 Vt[192 * 40];   // 15360 B (transposed V)
    __shared__ __align__(16) __nv_bfloat16 Ps[QT * 48];    //  6144 B
    __shared__ float denom[QT];
    __shared__ int   bpS[KT];

    const int h    = blockIdx.y;
    const int n0q  = blockIdx.x * QT;
    const int tid  = threadIdx.x;
    const int lane = tid & 31;
    const int w    = tid >> 5;
    const int g    = lane >> 2;     // group (row within 8)
    const int t    = lane & 3;      // thread-in-group (col pair)
    const int r    = w & 3;         // q-row group (16 rows)
    const int c    = w >> 2;        // column half

    // Q tile resident (bf16, padded rows)
    for (int u = tid; u < QT * 64; u += 256) {
        int row = u >> 6, du = u & 63;
        *((uint32_t*)(Qs + row * 136) + du) =
            *((const uint32_t*)(g_Qbf + (size_t)(n0q + row) * DDIM + h * 128) + du);
    }
    if (tid < QT) denom[tid] = 0.f;

    const int bh0 = batch_h[n0q + 16 * r + g];
    const int bh1 = batch_h[n0q + 16 * r + g + 8];

    float acc[12][4];
    #pragma unroll
    for (int nf = 0; nf < 12; nf++)
        #pragma unroll
        for (int q = 0; q < 4; q++) acc[nf][q] = 0.f;

    const float scale = 0.08838834764831845f;   // 1/sqrt(128)

    for (int m0 = 0; m0 < NPNT; m0 += KT) {
        // ---- fill K (row-major bf16) and V (transposed) ----
        for (int u = tid; u < KT * 64; u += 256) {
            int row = u >> 6, du = u & 63;
            *((uint32_t*)(Ks + row * 136) + du) =
                *((const uint32_t*)(g_Kbf + (size_t)(m0 + row) * DDIM + h * 128) + du);
        }
        for (int u = tid; u < KT * 96; u += 256) {
            int m = u / 96, e2 = u % 96;
            uint32_t v = *((const uint32_t*)(g_Vbf + (size_t)(m0 + m) * BERT + h * 192) + e2);
            Vt[(2 * e2)     * 40 + m] = __ushort_as_bfloat16((unsigned short)(v & 0xffffu));
            Vt[(2 * e2 + 1) * 40 + m] = __ushort_as_bfloat16((unsigned short)(v >> 16));
        }
        if (tid < KT) bpS[tid] = batch_p[m0 + tid];
        __syncthreads();

        // ---- stage 1: S[16 x 16] = Q Ktile^T (per warp) ----
        float s[2][4];
        #pragma unroll
        for (int nf = 0; nf < 2; nf++)
            #pragma unroll
            for (int q = 0; q < 4; q++) s[nf][q] = 0.f;

        const int qr = 16 * r, kc = 16 * c;
        #pragma unroll
        for (int kf = 0; kf < 8; kf++) {
            uint32_t a0 = *(const uint32_t*)(Qs + (qr + g)     * 136 + 16 * kf + 2 * t);
            uint32_t a1 = *(const uint32_t*)(Qs + (qr + g + 8) * 136 + 16 * kf + 2 * t);
            uint32_t a2 = *(const uint32_t*)(Qs + (qr + g)     * 136 + 16 * kf + 2 * t + 8);
            uint32_t a3 = *(const uint32_t*)(Qs + (qr + g + 8) * 136 + 16 * kf + 2 * t + 8);
            #pragma unroll
            for (int nf = 0; nf < 2; nf++) {
                uint32_t b0 = *(const uint32_t*)(Ks + (kc + 8 * nf + g) * 136 + 16 * kf + 2 * t);
                uint32_t b1 = *(const uint32_t*)(Ks + (kc + 8 * nf + g) * 136 + 16 * kf + 2 * t + 8);
                mma16816(s[nf][0], s[nf][1], s[nf][2], s[nf][3], a0, a1, a2, a3, b0, b1);
            }
        }

        // mask, exp, store P (bf16), rowsum
        float rs0 = 0.f, rs1 = 0.f;
        #pragma unroll
        for (int nf = 0; nf < 2; nf++) {
            int col = kc + 8 * nf + 2 * t;
            int bpa = bpS[col], bpb = bpS[col + 1];
            float e00 = (bh0 == bpa) ? 0.f : __expf(s[nf][0] * scale);
            float e01 = (bh0 == bpb) ? 0.f : __expf(s[nf][1] * scale);
            float e10 = (bh1 == bpa) ? 0.f : __expf(s[nf][2] * scale);
            float e11 = (bh1 == bpb) ? 0.f : __expf(s[nf][3] * scale);
            rs0 += e00 + e01;
            rs1 += e10 + e11;
            *(uint32_t*)(Ps + (qr + g)     * 48 + col) = packbf(e00, e01);
            *(uint32_t*)(Ps + (qr + g + 8) * 48 + col) = packbf(e10, e11);
        }
        rs0 += __shfl_xor_sync(0xffffffffu, rs0, 1);
        rs0 += __shfl_xor_sync(0xffffffffu, rs0, 2);
        rs1 += __shfl_xor_sync(0xffffffffu, rs1, 1);
        rs1 += __shfl_xor_sync(0xffffffffu, rs1, 2);
        if (t == 0) {
            atomicAdd(&denom[qr + g],     rs0);
            atomicAdd(&denom[qr + g + 8], rs1);
        }
        __syncthreads();

        // ---- stage 2: attended[16 x 96] += P[16 x 32] @ V[32 x 96] ----
        {
            const int e0 = 96 * c;
            #pragma unroll
            for (int kf = 0; kf < 2; kf++) {
                uint32_t a0 = *(const uint32_t*)(Ps + (qr + g)     * 48 + 16 * kf + 2 * t);
                uint32_t a1 = *(const uint32_t*)(Ps + (qr + g + 8) * 48 + 16 * kf + 2 * t);
                uint32_t a2 = *(const uint32_t*)(Ps + (qr + g)     * 48 + 16 * kf + 2 * t + 8);
                uint32_t a3 = *(const uint32_t*)(Ps + (qr + g + 8) * 48 + 16 * kf + 2 * t + 8);
                #pragma unroll
                for (int nf = 0; nf < 12; nf++) {
                    uint32_t b0 = *(const uint32_t*)(Vt + (e0 + 8 * nf + g) * 40 + 16 * kf + 2 * t);
                    uint32_t b1 = *(const uint32_t*)(Vt + (e0 + 8 * nf + g) * 40 + 16 * kf + 2 * t + 8);
                    mma16816(acc[nf][0], acc[nf][1], acc[nf][2], acc[nf][3],
                             a0, a1, a2, a3, b0, b1);
                }
            }
        }
        __syncthreads();
    }

    // ---- epilogue: divide by denom, store fp32 ----
    const float inv0 = 1.0f / denom[16 * r + g];
    const float inv1 = 1.0f / denom[16 * r + g + 8];
    const int row0 = n0q + 16 * r + g;
    const int row1 = row0 + 8;
    #pragma unroll
    for (int nf = 0; nf < 12; nf++) {
        int col = h * 192 + 96 * c + 8 * nf + 2 * t;
        float2 v0 = make_float2(acc[nf][0] * inv0, acc[nf][1] * inv0);
        float2 v1 = make_float2(acc[nf][2] * inv1, acc[nf][3] * inv1);
        *(float2*)(g_att + (size_t)row0 * BERT + col) = v0;
        *(float2*)(g_att + (size_t)row1 * BERT + col) = v1;
    }
}

// ---------------------------------------------------------------------------
// h1 = gelu(concat(ctx_h, lhs_h - att) @ W1 + b1)   M=4096 K=1280 N=256
// ---------------------------------------------------------------------------
__global__ __launch_bounds__(256)
void gemm_feats_kernel(const float* __restrict__ ctx_h, const float* __restrict__ lhs_h,
                       const float* __restrict__ W1, const float* __restrict__ b1) {
    const int N = 256, K = DDIM + BERT;
    __shared__ float As[GM_TK][GM_TM + 1];
    __shared__ float Bs[GM_TK][GM_TN];
    int tid = threadIdx.x;
    int m0 = blockIdx.y * GM_TM, n0 = blockIdx.x * GM_TN;
    int tx = tid & 15, ty = tid >> 4;
    float acc[8][4];
    #pragma unroll
    for (int i = 0; i < 8; i++)
        #pragma unroll
        for (int j = 0; j < 4; j++) acc[i][j] = 0.f;

    for (int k0 = 0; k0 < K; k0 += GM_TK) {
        #pragma unroll
        for (int i = 0; i < 8; i++) {
            int idx = tid + i * 256;
            int m = idx >> 4, k = idx & 15;
            int gm = m0 + m, gk = k0 + k;
            float a;
            if (gk < DDIM) a = ctx_h[(size_t)gm * DDIM + gk];
            else {
                int kk = gk - DDIM;
                a = lhs_h[(size_t)gm * BERT + kk] - g_att[(size_t)gm * BERT + kk];
            }
            As[k][m] = a;
        }
        #pragma unroll
        for (int i = 0; i < 4; i++) {
            int idx = tid + i * 256;
            int k = idx >> 6, n = idx & 63;
            Bs[k][n] = W1[(size_t)(k0 + k) * N + (n0 + n)];
        }
        __syncthreads();
        #pragma unroll
        for (int k = 0; k < GM_TK; k++) {
            float a[8], b[4];
            #pragma unroll
            for (int i = 0; i < 8; i++) a[i] = As[k][ty * 8 + i];
            #pragma unroll
            for (int j = 0; j < 4; j++) b[j] = Bs[k][tx * 4 + j];
            #pragma unroll
            for (int i = 0; i < 8; i++)
                #pragma unroll
                for (int j = 0; j < 4; j++) acc[i][j] += a[i] * b[j];
        }
        __syncthreads();
    }
    #pragma unroll
    for (int i = 0; i < 8; i++) {
        int m = m0 + ty * 8 + i;
        #pragma unroll
        for (int j = 0; j < 4; j++) {
            int n = n0 + tx * 4 + j;
            float x = acc[i][j] + b1[n];
            g_h1[(size_t)m * 256 + n] = x * normcdff(x);   // exact gelu
        }
    }
}

// ---------------------------------------------------------------------------
// h2 = h1@W2 ; LayerNorm(128) ; atomic pool.
// ---------------------------------------------------------------------------
__global__ __launch_bounds__(128)
void h2_ln_pool_kernel(const float* __restrict__ W2, const float* __restrict__ ln_g,
                       const float* __restrict__ ln_b, const int* __restrict__ batch_h) {
    int n = blockIdx.x;
    int c = threadIdx.x;
    __shared__ float h1s[256];
    __shared__ float red[4];
    h1s[c]       = g_h1[n * 256 + c];
    h1s[c + 128] = g_h1[n * 256 + 128 + c];
    __syncthreads();
    float acc = 0.f;
    #pragma unroll 8
    for (int k = 0; k < 256; k++) acc += h1s[k] * W2[k * 128 + c];

    float s = acc;
    #pragma unroll
    for (int o = 16; o > 0; o >>= 1) s += __shfl_xor_sync(0xffffffffu, s, o);
    if ((c & 31) == 0) red[c >> 5] = s;
    __syncthreads();
    float mu = (red[0] + red[1] + red[2] + red[3]) * (1.f / 128.f);
    __syncthreads();
    float d = acc - mu;
    float v = d * d;
    #pragma unroll
    for (int o = 16; o > 0; o >>= 1) v += __shfl_xor_sync(0xffffffffu, v, o);
    if ((c & 31) == 0) red[c >> 5] = v;
    __syncthreads();
    float var = (red[0] + red[1] + red[2] + red[3]) * (1.f / 128.f);
    float y = d * rsqrtf(var + 1e-5f) * ln_g[c] + ln_b[c];
    int b = batch_h[n];
    atomicAdd(&g_pooled[b * 128 + c], y);
    if (c == 0) atomicAdd(&g_cnt[b], 1.0f);
}

__global__ void final_kernel(const float* __restrict__ Wc, const float* __restrict__ bc,
                             float* __restrict__ out) {
    int t = threadIdx.x;
    if (t < NB * 3) {
        int b = t / 3, c = t % 3;
        float inv = 1.0f / fmaxf(g_cnt[b], 1.0f);
        float acc = 0.f;
        #pragma unroll 4
        for (int k = 0; k < 128; k++) acc += g_pooled[b * 128 + k] * Wc[k * 3 + c];
        out[b * 3 + c] = acc * inv + bc[c];
    }
}

// ---------------------------------------------------------------------------
extern "C" void kernel_launch(void* const* d_in, const int* in_sizes, int n_in,
                              void* d_out, int out_size) {
    const float* ctx_p   = (const float*)d_in[0];
    const float* ctx_h   = (const float*)d_in[1];
    const float* lhs_p   = (const float*)d_in[2];
    const float* lhs_h   = (const float*)d_in[3];
    const int*   batch_p = (const int*)d_in[4];   // int32 (JAX x64 disabled)
    const int*   batch_h = (const int*)d_in[5];
    const float* Wq = (const float*)d_in[6];
    const float* bq = (const float*)d_in[7];
    const float* Wk = (const float*)d_in[8];
    const float* bk = (const float*)d_in[9];
    const float* Wv = (const float*)d_in[10];
    const float* bv = (const float*)d_in[11];
    const float* W1 = (const float*)d_in[12];
    const float* b1 = (const float*)d_in[13];
    const float* W2 = (const float*)d_in[14];
    const float* ln_g = (const float*)d_in[15];
    const float* ln_b = (const float*)d_in[16];
    const float* Wc = (const float*)d_in[17];
    const float* bc = (const float*)d_in[18];
    float* out = (float*)d_out;

    zero_pool_kernel<<<16, 256>>>();

    gemm_bias_kernel<0, true ><<<dim3(DDIM / GM_TN, NHNT / GM_TM), 256>>>(
        ctx_h, Wq, bq, NHNT, DDIM, DDIM);
    gemm_bias_kernel<1, true ><<<dim3(DDIM / GM_TN, NPNT / GM_TM), 256>>>(
        ctx_p, Wk, bk, NPNT, DDIM, DDIM);
    gemm_bias_kernel<2, false><<<dim3(BERT / GM_TN, NPNT / GM_TM), 256>>>(
        lhs_p, Wv, bv, NPNT, BERT, BERT);

    attn_mma_kernel<<<dim3(NHNT / QT, HEADS), 256>>>(batch_p, batch_h);

    gemm_feats_kernel<<<dim3(256 / GM_TN, NHNT / GM_TM), 256>>>(ctx_h, lhs_h, W1, b1);

    h2_ln_pool_kernel<<<NHNT, 128>>>(W2, ln_g, ln_b, batch_h);

    final_kernel<<<1, 96>>>(Wc, bc, out);
}

// round 14
// speedup vs baseline: 3.0861x; 1.0749x over previous
#include <cuda_runtime.h>
#include <cuda_bf16.h>
#include <cstdint>
#include <cstddef>

// ---------------------------------------------------------------------------
// PairClassifier — Round 13: bf16 HMMA projections + bf16 HMMA attention
//   batch arrays are INT32.
// ---------------------------------------------------------------------------

#define NPNT 4096
#define NHNT 4096
#define DDIM 512
#define BERT 768
#define HEADS 4
#define NB 32

__device__ __nv_bfloat16 g_Qbf[NHNT * DDIM];
__device__ __nv_bfloat16 g_Kbf[NPNT * DDIM];
__device__ __nv_bfloat16 g_Vbf[NPNT * BERT];
__device__ float g_att[NHNT * BERT];
__device__ float g_h1[NHNT * 256];
__device__ float g_pooled[NB * 128];
__device__ float g_cnt[NB];

__global__ void zero_pool_kernel() {
    int i = blockIdx.x * blockDim.x + threadIdx.x;
    if (i < NB * 128) g_pooled[i] = 0.f;
    if (i < NB)       g_cnt[i]    = 0.f;
}

static __device__ __forceinline__ void mma16816(
    float& c0, float& c1, float& c2, float& c3,
    uint32_t a0, uint32_t a1, uint32_t a2, uint32_t a3,
    uint32_t b0, uint32_t b1) {
    asm volatile(
        "mma.sync.aligned.m16n8k16.row.col.f32.bf16.bf16.f32 "
        "{%0,%1,%2,%3}, {%4,%5,%6,%7}, {%8,%9}, {%0,%1,%2,%3};"
        : "+f"(c0), "+f"(c1), "+f"(c2), "+f"(c3)
        : "r"(a0), "r"(a1), "r"(a2), "r"(a3), "r"(b0), "r"(b1));
}

static __device__ __forceinline__ uint32_t packbf(float lo, float hi) {
    unsigned short ul = __bfloat16_as_ushort(__float2bfloat16(lo));
    unsigned short uh = __bfloat16_as_ushort(__float2bfloat16(hi));
    return (uint32_t)ul | ((uint32_t)uh << 16);
}

// ---------------------------------------------------------------------------
// bf16 HMMA projection GEMM: C = bf16(A) @ bf16(W) + bias, optional permute.
// Block tile 128x64, BK=32, 8 warps (each 32x32). fp32 accum.
// ---------------------------------------------------------------------------
#define PK 32
#define PST 40   // bf16 elements per smem row (32 + 8 pad)

template<int DST, bool PERM>
__global__ __launch_bounds__(256)
void gemm_bias_mma_kernel(const float* __restrict__ A, const float* __restrict__ W,
                          const float* __restrict__ bias, int M, int N, int K) {
    __nv_bfloat16* C = (DST == 0) ? g_Qbf : (DST == 1) ? g_Kbf : g_Vbf;
    __shared__ __align__(16) __nv_bfloat16 As[128 * PST];   // 10240 B
    __shared__ __align__(16) __nv_bfloat16 Ws[64 * PST];    //  5120 B (n-major, k contig)

    const int tid  = threadIdx.x;
    const int lane = tid & 31;
    const int w    = tid >> 5;
    const int g    = lane >> 2, t = lane & 3;
    const int wr   = w & 3, wc = w >> 2;
    const int m0   = blockIdx.y * 128, n0 = blockIdx.x * 64;

    float acc[2][4][4];
    #pragma unroll
    for (int mi = 0; mi < 2; mi++)
        #pragma unroll
        for (int ni = 0; ni < 4; ni++)
            #pragma unroll
            for (int q = 0; q < 4; q++) acc[mi][ni][q] = 0.f;

    for (int k0 = 0; k0 < K; k0 += PK) {
        // A tile 128x32 (coalesced reads over k)
        #pragma unroll
        for (int i = 0; i < 16; i++) {
            int idx = tid + i * 256;
            int m = idx >> 5, k = idx & 31;
            As[m * PST + k] = __float2bfloat16(A[(size_t)(m0 + m) * K + k0 + k]);
        }
        // W tile 32x64 -> transposed smem [n][k] (coalesced reads over n)
        #pragma unroll
        for (int i = 0; i < 8; i++) {
            int idx = tid + i * 256;
            int k = idx >> 6, n = idx & 63;
            Ws[n * PST + k] = __float2bfloat16(W[(size_t)(k0 + k) * N + n0 + n]);
        }
        __syncthreads();

        #pragma unroll
        for (int kf = 0; kf < 2; kf++) {
            uint32_t a[2][4], b[4][2];
            #pragma unroll
            for (int mi = 0; mi < 2; mi++) {
                const __nv_bfloat16* base = As + (wr * 32 + mi * 16 + g) * PST + kf * 16 + 2 * t;
                a[mi][0] = *(const uint32_t*)(base);
                a[mi][1] = *(const uint32_t*)(base + 8 * PST);
                a[mi][2] = *(const uint32_t*)(base + 8);
                a[mi][3] = *(const uint32_t*)(base + 8 * PST + 8);
            }
            #pragma unroll
            for (int ni = 0; ni < 4; ni++) {
                const __nv_bfloat16* base = Ws + (wc * 32 + ni * 8 + g) * PST + kf * 16 + 2 * t;
                b[ni][0] = *(const uint32_t*)(base);
                b[ni][1] = *(const uint32_t*)(base + 8);
            }
            #pragma unroll
            for (int mi = 0; mi < 2; mi++)
                #pragma unroll
                for (int ni = 0; ni < 4; ni++)
                    mma16816(acc[mi][ni][0], acc[mi][ni][1], acc[mi][ni][2], acc[mi][ni][3],
                             a[mi][0], a[mi][1], a[mi][2], a[mi][3], b[ni][0], b[ni][1]);
        }
        __syncthreads();
    }

    // epilogue: bias, optional head-permute, bf16 store
    #pragma unroll
    for (int mi = 0; mi < 2; mi++) {
        int row0 = m0 + wr * 32 + mi * 16 + g;
        #pragma unroll
        for (int ni = 0; ni < 4; ni++) {
            int ncol = n0 + wc * 32 + ni * 8 + 2 * t;
            #pragma unroll
            for (int q = 0; q < 4; q++) {
                int rr = row0 + (q >> 1) * 8;
                int nn = ncol + (q & 1);
                float v = acc[mi][ni][q] + bias[nn];
                int nc = PERM ? ((nn & 3) * 128 + (nn >> 2)) : nn;   // head-contiguous
                C[(size_t)rr * N + nc] = __float2bfloat16(v);
            }
        }
    }
}

// ---------------------------------------------------------------------------
// bf16 tensor-core attention (unchanged from Round 12 WIN).
// ---------------------------------------------------------------------------
#define QT 64
#define KT 32

__global__ __launch_bounds__(256, 2)
void attn_mma_kernel(const int* __restrict__ batch_p,
                     const int* __restrict__ batch_h) {
    __shared__ __align__(16) __nv_bfloat16 Qs[QT * 136];
    __shared__ __align__(16) __nv_bfloat16 Ks[KT * 136];
    __shared__ __align__(16) __nv_bfloat16 Vt[192 * 40];
    __shared__ __align__(16) __nv_bfloat16 Ps[QT * 48];
    __shared__ float denom[QT];
    __shared__ int   bpS[KT];

    const int h    = blockIdx.y;
    const int n0q  = blockIdx.x * QT;
    const int tid  = threadIdx.x;
    const int lane = tid & 31;
    const int w    = tid >> 5;
    const int g    = lane >> 2;
    const int t    = lane & 3;
    const int r    = w & 3;
    const int c    = w >> 2;

    for (int u = tid; u < QT * 64; u += 256) {
        int row = u >> 6, du = u & 63;
        *((uint32_t*)(Qs + row * 136) + du) =
            *((const uint32_t*)(g_Qbf + (size_t)(n0q + row) * DDIM + h * 128) + du);
    }
    if (tid < QT) denom[tid] = 0.f;

    const int bh0 = batch_h[n0q + 16 * r + g];
    const int bh1 = batch_h[n0q + 16 * r + g + 8];

    float acc[12][4];
    #pragma unroll
    for (int nf = 0; nf < 12; nf++)
        #pragma unroll
        for (int q = 0; q < 4; q++) acc[nf][q] = 0.f;

    const float scale = 0.08838834764831845f;

    for (int m0 = 0; m0 < NPNT; m0 += KT) {
        for (int u = tid; u < KT * 64; u += 256) {
            int row = u >> 6, du = u & 63;
            *((uint32_t*)(Ks + row * 136) + du) =
                *((const uint32_t*)(g_Kbf + (size_t)(m0 + row) * DDIM + h * 128) + du);
        }
        for (int u = tid; u < KT * 96; u += 256) {
            int m = u / 96, e2 = u % 96;
            uint32_t v = *((const uint32_t*)(g_Vbf + (size_t)(m0 + m) * BERT + h * 192) + e2);
            Vt[(2 * e2)     * 40 + m] = __ushort_as_bfloat16((unsigned short)(v & 0xffffu));
            Vt[(2 * e2 + 1) * 40 + m] = __ushort_as_bfloat16((unsigned short)(v >> 16));
        }
        if (tid < KT) bpS[tid] = batch_p[m0 + tid];
        __syncthreads();

        float s[2][4];
        #pragma unroll
        for (int nf = 0; nf < 2; nf++)
            #pragma unroll
            for (int q = 0; q < 4; q++) s[nf][q] = 0.f;

        const int qr = 16 * r, kc = 16 * c;
        #pragma unroll
        for (int kf = 0; kf < 8; kf++) {
            uint32_t a0 = *(const uint32_t*)(Qs + (qr + g)     * 136 + 16 * kf + 2 * t);
            uint32_t a1 = *(const uint32_t*)(Qs + (qr + g + 8) * 136 + 16 * kf + 2 * t);
            uint32_t a2 = *(const uint32_t*)(Qs + (qr + g)     * 136 + 16 * kf + 2 * t + 8);
            uint32_t a3 = *(const uint32_t*)(Qs + (qr + g + 8) * 136 + 16 * kf + 2 * t + 8);
            #pragma unroll
            for (int nf = 0; nf < 2; nf++) {
                uint32_t b0 = *(const uint32_t*)(Ks + (kc + 8 * nf + g) * 136 + 16 * kf + 2 * t);
                uint32_t b1 = *(const uint32_t*)(Ks + (kc + 8 * nf + g) * 136 + 16 * kf + 2 * t + 8);
                mma16816(s[nf][0], s[nf][1], s[nf][2], s[nf][3], a0, a1, a2, a3, b0, b1);
            }
        }

        float rs0 = 0.f, rs1 = 0.f;
        #pragma unroll
        for (int nf = 0; nf < 2; nf++) {
            int col = kc + 8 * nf + 2 * t;
            int bpa = bpS[col], bpb = bpS[col + 1];
            float e00 = (bh0 == bpa) ? 0.f : __expf(s[nf][0] * scale);
            float e01 = (bh0 == bpb) ? 0.f : __expf(s[nf][1] * scale);
            float e10 = (bh1 == bpa) ? 0.f : __expf(s[nf][2] * scale);
            float e11 = (bh1 == bpb) ? 0.f : __expf(s[nf][3] * scale);
            rs0 += e00 + e01;
            rs1 += e10 + e11;
            *(uint32_t*)(Ps + (qr + g)     * 48 + col) = packbf(e00, e01);
            *(uint32_t*)(Ps + (qr + g + 8) * 48 + col) = packbf(e10, e11);
        }
        rs0 += __shfl_xor_sync(0xffffffffu, rs0, 1);
        rs0 += __shfl_xor_sync(0xffffffffu, rs0, 2);
        rs1 += __shfl_xor_sync(0xffffffffu, rs1, 1);
        rs1 += __shfl_xor_sync(0xffffffffu, rs1, 2);
        if (t == 0) {
            atomicAdd(&denom[qr + g],     rs0);
            atomicAdd(&denom[qr + g + 8], rs1);
        }
        __syncthreads();

        {
            const int e0 = 96 * c;
            #pragma unroll
            for (int kf = 0; kf < 2; kf++) {
                uint32_t a0 = *(const uint32_t*)(Ps + (qr + g)     * 48 + 16 * kf + 2 * t);
                uint32_t a1 = *(const uint32_t*)(Ps + (qr + g + 8) * 48 + 16 * kf + 2 * t);
                uint32_t a2 = *(const uint32_t*)(Ps + (qr + g)     * 48 + 16 * kf + 2 * t + 8);
                uint32_t a3 = *(const uint32_t*)(Ps + (qr + g + 8) * 48 + 16 * kf + 2 * t + 8);
                #pragma unroll
                for (int nf = 0; nf < 12; nf++) {
                    uint32_t b0 = *(const uint32_t*)(Vt + (e0 + 8 * nf + g) * 40 + 16 * kf + 2 * t);
                    uint32_t b1 = *(const uint32_t*)(Vt + (e0 + 8 * nf + g) * 40 + 16 * kf + 2 * t + 8);
                    mma16816(acc[nf][0], acc[nf][1], acc[nf][2], acc[nf][3],
                             a0, a1, a2, a3, b0, b1);
                }
            }
        }
        __syncthreads();
    }

    const float inv0 = 1.0f / denom[16 * r + g];
    const float inv1 = 1.0f / denom[16 * r + g + 8];
    const int row0 = n0q + 16 * r + g;
    const int row1 = row0 + 8;
    #pragma unroll
    for (int nf = 0; nf < 12; nf++) {
        int col = h * 192 + 96 * c + 8 * nf + 2 * t;
        float2 v0 = make_float2(acc[nf][0] * inv0, acc[nf][1] * inv0);
        float2 v1 = make_float2(acc[nf][2] * inv1, acc[nf][3] * inv1);
        *(float2*)(g_att + (size_t)row0 * BERT + col) = v0;
        *(float2*)(g_att + (size_t)row1 * BERT + col) = v1;
    }
}

// ---------------------------------------------------------------------------
// h1 = gelu(concat(ctx_h, lhs_h - att) @ W1 + b1)   M=4096 K=1280 N=256  (fp32)
// ---------------------------------------------------------------------------
#define GM_TM 128
#define GM_TN 64
#define GM_TK 16

__global__ __launch_bounds__(256)
void gemm_feats_kernel(const float* __restrict__ ctx_h, const float* __restrict__ lhs_h,
                       const float* __restrict__ W1, const float* __restrict__ b1) {
    const int N = 256, K = DDIM + BERT;
    __shared__ float As[GM_TK][GM_TM + 1];
    __shared__ float Bs[GM_TK][GM_TN];
    int tid = threadIdx.x;
    int m0 = blockIdx.y * GM_TM, n0 = blockIdx.x * GM_TN;
    int tx = tid & 15, ty = tid >> 4;
    float acc[8][4];
    #pragma unroll
    for (int i = 0; i < 8; i++)
        #pragma unroll
        for (int j = 0; j < 4; j++) acc[i][j] = 0.f;

    for (int k0 = 0; k0 < K; k0 += GM_TK) {
        #pragma unroll
        for (int i = 0; i < 8; i++) {
            int idx = tid + i * 256;
            int m = idx >> 4, k = idx & 15;
            int gm = m0 + m, gk = k0 + k;
            float a;
            if (gk < DDIM) a = ctx_h[(size_t)gm * DDIM + gk];
            else {
                int kk = gk - DDIM;
                a = lhs_h[(size_t)gm * BERT + kk] - g_att[(size_t)gm * BERT + kk];
            }
            As[k][m] = a;
        }
        #pragma unroll
        for (int i = 0; i < 4; i++) {
            int idx = tid + i * 256;
            int k = idx >> 6, n = idx & 63;
            Bs[k][n] = W1[(size_t)(k0 + k) * N + (n0 + n)];
        }
        __syncthreads();
        #pragma unroll
        for (int k = 0; k < GM_TK; k++) {
            float a[8], b[4];
            #pragma unroll
            for (int i = 0; i < 8; i++) a[i] = As[k][ty * 8 + i];
            #pragma unroll
            for (int j = 0; j < 4; j++) b[j] = Bs[k][tx * 4 + j];
            #pragma unroll
            for (int i = 0; i < 8; i++)
                #pragma unroll
                for (int j = 0; j < 4; j++) acc[i][j] += a[i] * b[j];
        }
        __syncthreads();
    }
    #pragma unroll
    for (int i = 0; i < 8; i++) {
        int m = m0 + ty * 8 + i;
        #pragma unroll
        for (int j = 0; j < 4; j++) {
            int n = n0 + tx * 4 + j;
            float x = acc[i][j] + b1[n];
            g_h1[(size_t)m * 256 + n] = x * normcdff(x);
        }
    }
}

// ---------------------------------------------------------------------------
// h2 = h1@W2 ; LayerNorm(128) ; atomic pool.
// ---------------------------------------------------------------------------
__global__ __launch_bounds__(128)
void h2_ln_pool_kernel(const float* __restrict__ W2, const float* __restrict__ ln_g,
                       const float* __restrict__ ln_b, const int* __restrict__ batch_h) {
    int n = blockIdx.x;
    int c = threadIdx.x;
    __shared__ float h1s[256];
    __shared__ float red[4];
    h1s[c]       = g_h1[n * 256 + c];
    h1s[c + 128] = g_h1[n * 256 + 128 + c];
    __syncthreads();
    float acc = 0.f;
    #pragma unroll 8
    for (int k = 0; k < 256; k++) acc += h1s[k] * W2[k * 128 + c];

    float s = acc;
    #pragma unroll
    for (int o = 16; o > 0; o >>= 1) s += __shfl_xor_sync(0xffffffffu, s, o);
    if ((c & 31) == 0) red[c >> 5] = s;
    __syncthreads();
    float mu = (red[0] + red[1] + red[2] + red[3]) * (1.f / 128.f);
    __syncthreads();
    float d = acc - mu;
    float v = d * d;
    #pragma unroll
    for (int o = 16; o > 0; o >>= 1) v += __shfl_xor_sync(0xffffffffu, v, o);
    if ((c & 31) == 0) red[c >> 5] = v;
    __syncthreads();
    float var = (red[0] + red[1] + red[2] + red[3]) * (1.f / 128.f);
    float y = d * rsqrtf(var + 1e-5f) * ln_g[c] + ln_b[c];
    int b = batch_h[n];
    atomicAdd(&g_pooled[b * 128 + c], y);
    if (c == 0) atomicAdd(&g_cnt[b], 1.0f);
}

__global__ void final_kernel(const float* __restrict__ Wc, const float* __restrict__ bc,
                             float* __restrict__ out) {
    int t = threadIdx.x;
    if (t < NB * 3) {
        int b = t / 3, c = t % 3;
        float inv = 1.0f / fmaxf(g_cnt[b], 1.0f);
        float acc = 0.f;
        #pragma unroll 4
        for (int k = 0; k < 128; k++) acc += g_pooled[b * 128 + k] * Wc[k * 3 + c];
        out[b * 3 + c] = acc * inv + bc[c];
    }
}

// ---------------------------------------------------------------------------
extern "C" void kernel_launch(void* const* d_in, const int* in_sizes, int n_in,
                              void* d_out, int out_size) {
    const float* ctx_p   = (const float*)d_in[0];
    const float* ctx_h   = (const float*)d_in[1];
    const float* lhs_p   = (const float*)d_in[2];
    const float* lhs_h   = (const float*)d_in[3];
    const int*   batch_p = (const int*)d_in[4];   // int32 (JAX x64 disabled)
    const int*   batch_h = (const int*)d_in[5];
    const float* Wq = (const float*)d_in[6];
    const float* bq = (const float*)d_in[7];
    const float* Wk = (const float*)d_in[8];
    const float* bk = (const float*)d_in[9];
    const float* Wv = (const float*)d_in[10];
    const float* bv = (const float*)d_in[11];
    const float* W1 = (const float*)d_in[12];
    const float* b1 = (const float*)d_in[13];
    const float* W2 = (const float*)d_in[14];
    const float* ln_g = (const float*)d_in[15];
    const float* ln_b = (const float*)d_in[16];
    const float* Wc = (const float*)d_in[17];
    const float* bc = (const float*)d_in[18];
    float* out = (float*)d_out;

    zero_pool_kernel<<<16, 256>>>();

    gemm_bias_mma_kernel<0, true ><<<dim3(DDIM / 64, NHNT / 128), 256>>>(
        ctx_h, Wq, bq, NHNT, DDIM, DDIM);
    gemm_bias_mma_kernel<1, true ><<<dim3(DDIM / 64, NPNT / 128), 256>>>(
        ctx_p, Wk, bk, NPNT, DDIM, DDIM);
    gemm_bias_mma_kernel<2, false><<<dim3(BERT / 64, NPNT / 128), 256>>>(
        lhs_p, Wv, bv, NPNT, BERT, BERT);

    attn_mma_kernel<<<dim3(NHNT / QT, HEADS), 256>>>(batch_p, batch_h);

    gemm_feats_kernel<<<dim3(256 / GM_TN, NHNT / GM_TM), 256>>>(ctx_h, lhs_h, W1, b1);

    h2_ln_pool_kernel<<<NHNT, 128>>>(W2, ln_g, ln_b, batch_h);

    final_kernel<<<1, 96>>>(Wc, bc, out);
}

// round 15
// speedup vs baseline: 3.4766x; 1.1266x over previous
#include <cuda_runtime.h>
#include <cuda_bf16.h>
#include <cstdint>
#include <cstddef>

// ---------------------------------------------------------------------------
// PairClassifier — Round 15: pre-transposed V + dual-chain stage1
//   batch arrays are INT32.
// ---------------------------------------------------------------------------

#define NPNT 4096
#define NHNT 4096
#define DDIM 512
#define BERT 768
#define HEADS 4
#define NB 32

__device__ __nv_bfloat16 g_Qbf[NHNT * DDIM];
__device__ __nv_bfloat16 g_Kbf[NPNT * DDIM];
__device__ __nv_bfloat16 g_Vbf[NPNT * BERT];
__device__ __nv_bfloat16 g_Vt [BERT * NPNT];   // [dim][token], dim = h*192+e
__device__ float g_att[NHNT * BERT];
__device__ float g_h1[NHNT * 256];
__device__ float g_pooled[NB * 128];
__device__ float g_cnt[NB];

__global__ void zero_pool_kernel() {
    int i = blockIdx.x * blockDim.x + threadIdx.x;
    if (i < NB * 128) g_pooled[i] = 0.f;
    if (i < NB)       g_cnt[i]    = 0.f;
}

static __device__ __forceinline__ void mma16816(
    float& c0, float& c1, float& c2, float& c3,
    uint32_t a0, uint32_t a1, uint32_t a2, uint32_t a3,
    uint32_t b0, uint32_t b1) {
    asm volatile(
        "mma.sync.aligned.m16n8k16.row.col.f32.bf16.bf16.f32 "
        "{%0,%1,%2,%3}, {%4,%5,%6,%7}, {%8,%9}, {%0,%1,%2,%3};"
        : "+f"(c0), "+f"(c1), "+f"(c2), "+f"(c3)
        : "r"(a0), "r"(a1), "r"(a2), "r"(a3), "r"(b0), "r"(b1));
}

static __device__ __forceinline__ uint32_t packbf(float lo, float hi) {
    unsigned short ul = __bfloat16_as_ushort(__float2bfloat16(lo));
    unsigned short uh = __bfloat16_as_ushort(__float2bfloat16(hi));
    return (uint32_t)ul | ((uint32_t)uh << 16);
}

// ---------------------------------------------------------------------------
// V transpose: g_Vbf[token][dim] -> g_Vt[dim][token].  32x32 tiles.
// ---------------------------------------------------------------------------
__global__ __launch_bounds__(256)
void transpose_v_kernel() {
    __shared__ __nv_bfloat16 tile[32][33];
    const int t0 = blockIdx.x * 32;          // token base
    const int d0 = blockIdx.y * 32;          // dim base
    const int tx = threadIdx.x & 31;
    const int ry = threadIdx.x >> 5;         // 0..7
    #pragma unroll
    for (int j = 0; j < 4; j++) {
        int tok = ry + 8 * j;
        tile[tok][tx] = g_Vbf[(size_t)(t0 + tok) * BERT + d0 + tx];
    }
    __syncthreads();
    #pragma unroll
    for (int j = 0; j < 4; j++) {
        int d = ry + 8 * j;
        g_Vt[(size_t)(d0 + d) * NPNT + t0 + tx] = tile[tx][d];
    }
}

// ---------------------------------------------------------------------------
// bf16 HMMA projection GEMM (unchanged from Round 14 WIN).
// ---------------------------------------------------------------------------
#define PK 32
#define PST 40

template<int DST, bool PERM>
__global__ __launch_bounds__(256)
void gemm_bias_mma_kernel(const float* __restrict__ A, const float* __restrict__ W,
                          const float* __restrict__ bias, int M, int N, int K) {
    __nv_bfloat16* C = (DST == 0) ? g_Qbf : (DST == 1) ? g_Kbf : g_Vbf;
    __shared__ __align__(16) __nv_bfloat16 As[128 * PST];
    __shared__ __align__(16) __nv_bfloat16 Ws[64 * PST];

    const int tid  = threadIdx.x;
    const int lane = tid & 31;
    const int w    = tid >> 5;
    const int g    = lane >> 2, t = lane & 3;
    const int wr   = w & 3, wc = w >> 2;
    const int m0   = blockIdx.y * 128, n0 = blockIdx.x * 64;

    float acc[2][4][4];
    #pragma unroll
    for (int mi = 0; mi < 2; mi++)
        #pragma unroll
        for (int ni = 0; ni < 4; ni++)
            #pragma unroll
            for (int q = 0; q < 4; q++) acc[mi][ni][q] = 0.f;

    for (int k0 = 0; k0 < K; k0 += PK) {
        #pragma unroll
        for (int i = 0; i < 16; i++) {
            int idx = tid + i * 256;
            int m = idx >> 5, k = idx & 31;
            As[m * PST + k] = __float2bfloat16(A[(size_t)(m0 + m) * K + k0 + k]);
        }
        #pragma unroll
        for (int i = 0; i < 8; i++) {
            int idx = tid + i * 256;
            int k = idx >> 6, n = idx & 63;
            Ws[n * PST + k] = __float2bfloat16(W[(size_t)(k0 + k) * N + n0 + n]);
        }
        __syncthreads();

        #pragma unroll
        for (int kf = 0; kf < 2; kf++) {
            uint32_t a[2][4], b[4][2];
            #pragma unroll
            for (int mi = 0; mi < 2; mi++) {
                const __nv_bfloat16* base = As + (wr * 32 + mi * 16 + g) * PST + kf * 16 + 2 * t;
                a[mi][0] = *(const uint32_t*)(base);
                a[mi][1] = *(const uint32_t*)(base + 8 * PST);
                a[mi][2] = *(const uint32_t*)(base + 8);
                a[mi][3] = *(const uint32_t*)(base + 8 * PST + 8);
            }
            #pragma unroll
            for (int ni = 0; ni < 4; ni++) {
                const __nv_bfloat16* base = Ws + (wc * 32 + ni * 8 + g) * PST + kf * 16 + 2 * t;
                b[ni][0] = *(const uint32_t*)(base);
                b[ni][1] = *(const uint32_t*)(base + 8);
            }
            #pragma unroll
            for (int mi = 0; mi < 2; mi++)
                #pragma unroll
                for (int ni = 0; ni < 4; ni++)
                    mma16816(acc[mi][ni][0], acc[mi][ni][1], acc[mi][ni][2], acc[mi][ni][3],
                             a[mi][0], a[mi][1], a[mi][2], a[mi][3], b[ni][0], b[ni][1]);
        }
        __syncthreads();
    }

    #pragma unroll
    for (int mi = 0; mi < 2; mi++) {
        int row0 = m0 + wr * 32 + mi * 16 + g;
        #pragma unroll
        for (int ni = 0; ni < 4; ni++) {
            int ncol = n0 + wc * 32 + ni * 8 + 2 * t;
            #pragma unroll
            for (int q = 0; q < 4; q++) {
                int rr = row0 + (q >> 1) * 8;
                int nn = ncol + (q & 1);
                float v = acc[mi][ni][q] + bias[nn];
                int nc = PERM ? ((nn & 3) * 128 + (nn >> 2)) : nn;
                C[(size_t)rr * N + nc] = __float2bfloat16(v);
            }
        }
    }
}

// ---------------------------------------------------------------------------
// bf16 tensor-core attention. Round 15: coalesced V fill + dual-chain stage1.
// ---------------------------------------------------------------------------
#define QT 64
#define KT 32

__global__ __launch_bounds__(256, 2)
void attn_mma_kernel(const int* __restrict__ batch_p,
                     const int* __restrict__ batch_h) {
    __shared__ __align__(16) __nv_bfloat16 Qs[QT * 136];
    __shared__ __align__(16) __nv_bfloat16 Ks[KT * 136];
    __shared__ __align__(16) __nv_bfloat16 Vt[192 * 40];
    __shared__ __align__(16) __nv_bfloat16 Ps[QT * 48];
    __shared__ float denom[QT];
    __shared__ int   bpS[KT];

    const int h    = blockIdx.y;
    const int n0q  = blockIdx.x * QT;
    const int tid  = threadIdx.x;
    const int lane = tid & 31;
    const int w    = tid >> 5;
    const int g    = lane >> 2;
    const int t    = lane & 3;
    const int r    = w & 3;
    const int c    = w >> 2;

    for (int u = tid; u < QT * 64; u += 256) {
        int row = u >> 6, du = u & 63;
        *((uint32_t*)(Qs + row * 136) + du) =
            *((const uint32_t*)(g_Qbf + (size_t)(n0q + row) * DDIM + h * 128) + du);
    }
    if (tid < QT) denom[tid] = 0.f;

    const int bh0 = batch_h[n0q + 16 * r + g];
    const int bh1 = batch_h[n0q + 16 * r + g + 8];

    float acc[12][4];
    #pragma unroll
    for (int nf = 0; nf < 12; nf++)
        #pragma unroll
        for (int q = 0; q < 4; q++) acc[nf][q] = 0.f;

    const float scale = 0.08838834764831845f;

    for (int m0 = 0; m0 < NPNT; m0 += KT) {
        for (int u = tid; u < KT * 64; u += 256) {
            int row = u >> 6, du = u & 63;
            *((uint32_t*)(Ks + row * 136) + du) =
                *((const uint32_t*)(g_Kbf + (size_t)(m0 + row) * DDIM + h * 128) + du);
        }
        // V tile: pre-transposed, coalesced word copy (12 words/thread)
        for (int u = tid; u < 192 * 16; u += 256) {
            int row = u >> 4, du = u & 15;
            *((uint32_t*)(Vt + row * 40) + du) =
                *((const uint32_t*)(g_Vt + (size_t)(h * 192 + row) * NPNT + m0) + du);
        }
        if (tid < KT) bpS[tid] = batch_p[m0 + tid];
        __syncthreads();

        // ---- stage 1: dual accumulation chains (kf even -> s, odd -> s2) ----
        float s[2][4], s2[2][4];
        #pragma unroll
        for (int nf = 0; nf < 2; nf++)
            #pragma unroll
            for (int q = 0; q < 4; q++) { s[nf][q] = 0.f; s2[nf][q] = 0.f; }

        const int qr = 16 * r, kc = 16 * c;
        #pragma unroll
        for (int kf = 0; kf < 8; kf++) {
            uint32_t a0 = *(const uint32_t*)(Qs + (qr + g)     * 136 + 16 * kf + 2 * t);
            uint32_t a1 = *(const uint32_t*)(Qs + (qr + g + 8) * 136 + 16 * kf + 2 * t);
            uint32_t a2 = *(const uint32_t*)(Qs + (qr + g)     * 136 + 16 * kf + 2 * t + 8);
            uint32_t a3 = *(const uint32_t*)(Qs + (qr + g + 8) * 136 + 16 * kf + 2 * t + 8);
            #pragma unroll
            for (int nf = 0; nf < 2; nf++) {
                uint32_t b0 = *(const uint32_t*)(Ks + (kc + 8 * nf + g) * 136 + 16 * kf + 2 * t);
                uint32_t b1 = *(const uint32_t*)(Ks + (kc + 8 * nf + g) * 136 + 16 * kf + 2 * t + 8);
                if (kf & 1)
                    mma16816(s2[nf][0], s2[nf][1], s2[nf][2], s2[nf][3], a0, a1, a2, a3, b0, b1);
                else
                    mma16816(s[nf][0],  s[nf][1],  s[nf][2],  s[nf][3],  a0, a1, a2, a3, b0, b1);
            }
        }

        float rs0 = 0.f, rs1 = 0.f;
        #pragma unroll
        for (int nf = 0; nf < 2; nf++) {
            int col = kc + 8 * nf + 2 * t;
            int bpa = bpS[col], bpb = bpS[col + 1];
            float e00 = (bh0 == bpa) ? 0.f : __expf((s[nf][0] + s2[nf][0]) * scale);
            float e01 = (bh0 == bpb) ? 0.f : __expf((s[nf][1] + s2[nf][1]) * scale);
            float e10 = (bh1 == bpa) ? 0.f : __expf((s[nf][2] + s2[nf][2]) * scale);
            float e11 = (bh1 == bpb) ? 0.f : __expf((s[nf][3] + s2[nf][3]) * scale);
            rs0 += e00 + e01;
            rs1 += e10 + e11;
            *(uint32_t*)(Ps + (qr + g)     * 48 + col) = packbf(e00, e01);
            *(uint32_t*)(Ps + (qr + g + 8) * 48 + col) = packbf(e10, e11);
        }
        rs0 += __shfl_xor_sync(0xffffffffu, rs0, 1);
        rs0 += __shfl_xor_sync(0xffffffffu, rs0, 2);
        rs1 += __shfl_xor_sync(0xffffffffu, rs1, 1);
        rs1 += __shfl_xor_sync(0xffffffffu, rs1, 2);
        if (t == 0) {
            atomicAdd(&denom[qr + g],     rs0);
            atomicAdd(&denom[qr + g + 8], rs1);
        }
        __syncthreads();

        // ---- stage 2: attended += P @ V ----
        {
            const int e0 = 96 * c;
            #pragma unroll
            for (int kf = 0; kf < 2; kf++) {
                uint32_t a0 = *(const uint32_t*)(Ps + (qr + g)     * 48 + 16 * kf + 2 * t);
                uint32_t a1 = *(const uint32_t*)(Ps + (qr + g + 8) * 48 + 16 * kf + 2 * t);
                uint32_t a2 = *(const uint32_t*)(Ps + (qr + g)     * 48 + 16 * kf + 2 * t + 8);
                uint32_t a3 = *(const uint32_t*)(Ps + (qr + g + 8) * 48 + 16 * kf + 2 * t + 8);
                #pragma unroll
                for (int nf = 0; nf < 12; nf++) {
                    uint32_t b0 = *(const uint32_t*)(Vt + (e0 + 8 * nf + g) * 40 + 16 * kf + 2 * t);
                    uint32_t b1 = *(const uint32_t*)(Vt + (e0 + 8 * nf + g) * 40 + 16 * kf + 2 * t + 8);
                    mma16816(acc[nf][0], acc[nf][1], acc[nf][2], acc[nf][3],
                             a0, a1, a2, a3, b0, b1);
                }
            }
        }
        __syncthreads();
    }

    const float inv0 = 1.0f / denom[16 * r + g];
    const float inv1 = 1.0f / denom[16 * r + g + 8];
    const int row0 = n0q + 16 * r + g;
    const int row1 = row0 + 8;
    #pragma unroll
    for (int nf = 0; nf < 12; nf++) {
        int col = h * 192 + 96 * c + 8 * nf + 2 * t;
        float2 v0 = make_float2(acc[nf][0] * inv0, acc[nf][1] * inv0);
        float2 v1 = make_float2(acc[nf][2] * inv1, acc[nf][3] * inv1);
        *(float2*)(g_att + (size_t)row0 * BERT + col) = v0;
        *(float2*)(g_att + (size_t)row1 * BERT + col) = v1;
    }
}

// ---------------------------------------------------------------------------
// h1 = gelu(concat(ctx_h, lhs_h - att) @ W1 + b1)   (fp32)
// ---------------------------------------------------------------------------
#define GM_TM 128
#define GM_TN 64
#define GM_TK 16

__global__ __launch_bounds__(256)
void gemm_feats_kernel(const float* __restrict__ ctx_h, const float* __restrict__ lhs_h,
                       const float* __restrict__ W1, const float* __restrict__ b1) {
    const int N = 256, K = DDIM + BERT;
    __shared__ float As[GM_TK][GM_TM + 1];
    __shared__ float Bs[GM_TK][GM_TN];
    int tid = threadIdx.x;
    int m0 = blockIdx.y * GM_TM, n0 = blockIdx.x * GM_TN;
    int tx = tid & 15, ty = tid >> 4;
    float acc[8][4];
    #pragma unroll
    for (int i = 0; i < 8; i++)
        #pragma unroll
        for (int j = 0; j < 4; j++) acc[i][j] = 0.f;

    for (int k0 = 0; k0 < K; k0 += GM_TK) {
        #pragma unroll
        for (int i = 0; i < 8; i++) {
            int idx = tid + i * 256;
            int m = idx >> 4, k = idx & 15;
            int gm = m0 + m, gk = k0 + k;
            float a;
            if (gk < DDIM) a = ctx_h[(size_t)gm * DDIM + gk];
            else {
                int kk = gk - DDIM;
                a = lhs_h[(size_t)gm * BERT + kk] - g_att[(size_t)gm * BERT + kk];
            }
            As[k][m] = a;
        }
        #pragma unroll
        for (int i = 0; i < 4; i++) {
            int idx = tid + i * 256;
            int k = idx >> 6, n = idx & 63;
            Bs[k][n] = W1[(size_t)(k0 + k) * N + (n0 + n)];
        }
        __syncthreads();
        #pragma unroll
        for (int k = 0; k < GM_TK; k++) {
            float a[8], b[4];
            #pragma unroll
            for (int i = 0; i < 8; i++) a[i] = As[k][ty * 8 + i];
            #pragma unroll
            for (int j = 0; j < 4; j++) b[j] = Bs[k][tx * 4 + j];
            #pragma unroll
            for (int i = 0; i < 8; i++)
                #pragma unroll
                for (int j = 0; j < 4; j++) acc[i][j] += a[i] * b[j];
        }
        __syncthreads();
    }
    #pragma unroll
    for (int i = 0; i < 8; i++) {
        int m = m0 + ty * 8 + i;
        #pragma unroll
        for (int j = 0; j < 4; j++) {
            int n = n0 + tx * 4 + j;
            float x = acc[i][j] + b1[n];
            g_h1[(size_t)m * 256 + n] = x * normcdff(x);
        }
    }
}

// ---------------------------------------------------------------------------
// h2 = h1@W2 ; LayerNorm(128) ; atomic pool.
// ---------------------------------------------------------------------------
__global__ __launch_bounds__(128)
void h2_ln_pool_kernel(const float* __restrict__ W2, const float* __restrict__ ln_g,
                       const float* __restrict__ ln_b, const int* __restrict__ batch_h) {
    int n = blockIdx.x;
    int c = threadIdx.x;
    __shared__ float h1s[256];
    __shared__ float red[4];
    h1s[c]       = g_h1[n * 256 + c];
    h1s[c + 128] = g_h1[n * 256 + 128 + c];
    __syncthreads();
    float acc = 0.f;
    #pragma unroll 8
    for (int k = 0; k < 256; k++) acc += h1s[k] * W2[k * 128 + c];

    float s = acc;
    #pragma unroll
    for (int o = 16; o > 0; o >>= 1) s += __shfl_xor_sync(0xffffffffu, s, o);
    if ((c & 31) == 0) red[c >> 5] = s;
    __syncthreads();
    float mu = (red[0] + red[1] + red[2] + red[3]) * (1.f / 128.f);
    __syncthreads();
    float d = acc - mu;
    float v = d * d;
    #pragma unroll
    for (int o = 16; o > 0; o >>= 1) v += __shfl_xor_sync(0xffffffffu, v, o);
    if ((c & 31) == 0) red[c >> 5] = v;
    __syncthreads();
    float var = (red[0] + red[1] + red[2] + red[3]) * (1.f / 128.f);
    float y = d * rsqrtf(var + 1e-5f) * ln_g[c] + ln_b[c];
    int b = batch_h[n];
    atomicAdd(&g_pooled[b * 128 + c], y);
    if (c == 0) atomicAdd(&g_cnt[b], 1.0f);
}

__global__ void final_kernel(const float* __restrict__ Wc, const float* __restrict__ bc,
                             float* __restrict__ out) {
    int t = threadIdx.x;
    if (t < NB * 3) {
        int b = t / 3, c = t % 3;
        float inv = 1.0f / fmaxf(g_cnt[b], 1.0f);
        float acc = 0.f;
        #pragma unroll 4
        for (int k = 0; k < 128; k++) acc += g_pooled[b * 128 + k] * Wc[k * 3 + c];
        out[b * 3 + c] = acc * inv + bc[c];
    }
}

// ---------------------------------------------------------------------------
extern "C" void kernel_launch(void* const* d_in, const int* in_sizes, int n_in,
                              void* d_out, int out_size) {
    const float* ctx_p   = (const float*)d_in[0];
    const float* ctx_h   = (const float*)d_in[1];
    const float* lhs_p   = (const float*)d_in[2];
    const float* lhs_h   = (const float*)d_in[3];
    const int*   batch_p = (const int*)d_in[4];   // int32 (JAX x64 disabled)
    const int*   batch_h = (const int*)d_in[5];
    const float* Wq = (const float*)d_in[6];
    const float* bq = (const float*)d_in[7];
    const float* Wk = (const float*)d_in[8];
    const float* bk = (const float*)d_in[9];
    const float* Wv = (const float*)d_in[10];
    const float* bv = (const float*)d_in[11];
    const float* W1 = (const float*)d_in[12];
    const float* b1 = (const float*)d_in[13];
    const float* W2 = (const float*)d_in[14];
    const float* ln_g = (const float*)d_in[15];
    const float* ln_b = (const float*)d_in[16];
    const float* Wc = (const float*)d_in[17];
    const float* bc = (const float*)d_in[18];
    float* out = (float*)d_out;

    zero_pool_kernel<<<16, 256>>>();

    gemm_bias_mma_kernel<0, true ><<<dim3(DDIM / 64, NHNT / 128), 256>>>(
        ctx_h, Wq, bq, NHNT, DDIM, DDIM);
    gemm_bias_mma_kernel<1, true ><<<dim3(DDIM / 64, NPNT / 128), 256>>>(
        ctx_p, Wk, bk, NPNT, DDIM, DDIM);
    gemm_bias_mma_kernel<2, false><<<dim3(BERT / 64, NPNT / 128), 256>>>(
        lhs_p, Wv, bv, NPNT, BERT, BERT);

    transpose_v_kernel<<<dim3(NPNT / 32, BERT / 32), 256>>>();

    attn_mma_kernel<<<dim3(NHNT / QT, HEADS), 256>>>(batch_p, batch_h);

    gemm_feats_kernel<<<dim3(256 / GM_TN, NHNT / GM_TM), 256>>>(ctx_h, lhs_h, W1, b1);

    h2_ln_pool_kernel<<<NHNT, 128>>>(W2, ln_g, ln_b, batch_h);

    final_kernel<<<1, 96>>>(Wc, bc, out);
}

// round 17
// speedup vs baseline: 3.8330x; 1.1025x over previous
#include <cuda_runtime.h>
#include <cuda_bf16.h>
#include <cstdint>
#include <cstddef>

// ---------------------------------------------------------------------------
// PairClassifier — Round 16: projection occupancy (2 blk/SM) +
//   attention register-prefetch double buffering.
//   batch arrays are INT32.
// ---------------------------------------------------------------------------

#define NPNT 4096
#define NHNT 4096
#define DDIM 512
#define BERT 768
#define HEADS 4
#define NB 32

__device__ __nv_bfloat16 g_Qbf[NHNT * DDIM];
__device__ __nv_bfloat16 g_Kbf[NPNT * DDIM];
__device__ __nv_bfloat16 g_Vbf[NPNT * BERT];
__device__ __nv_bfloat16 g_Vt [BERT * NPNT];   // [dim][token]
__device__ float g_att[NHNT * BERT];
__device__ float g_h1[NHNT * 256];
__device__ float g_pooled[NB * 128];
__device__ float g_cnt[NB];

__global__ void zero_pool_kernel() {
    int i = blockIdx.x * blockDim.x + threadIdx.x;
    if (i < NB * 128) g_pooled[i] = 0.f;
    if (i < NB)       g_cnt[i]    = 0.f;
}

static __device__ __forceinline__ void mma16816(
    float& c0, float& c1, float& c2, float& c3,
    uint32_t a0, uint32_t a1, uint32_t a2, uint32_t a3,
    uint32_t b0, uint32_t b1) {
    asm volatile(
        "mma.sync.aligned.m16n8k16.row.col.f32.bf16.bf16.f32 "
        "{%0,%1,%2,%3}, {%4,%5,%6,%7}, {%8,%9}, {%0,%1,%2,%3};"
        : "+f"(c0), "+f"(c1), "+f"(c2), "+f"(c3)
        : "r"(a0), "r"(a1), "r"(a2), "r"(a3), "r"(b0), "r"(b1));
}

static __device__ __forceinline__ uint32_t packbf(float lo, float hi) {
    unsigned short ul = __bfloat16_as_ushort(__float2bfloat16(lo));
    unsigned short uh = __bfloat16_as_ushort(__float2bfloat16(hi));
    return (uint32_t)ul | ((uint32_t)uh << 16);
}

// ---------------------------------------------------------------------------
// V transpose: g_Vbf[token][dim] -> g_Vt[dim][token].
// ---------------------------------------------------------------------------
__global__ __launch_bounds__(256)
void transpose_v_kernel() {
    __shared__ __nv_bfloat16 tile[32][33];
    const int t0 = blockIdx.x * 32;
    const int d0 = blockIdx.y * 32;
    const int tx = threadIdx.x & 31;
    const int ry = threadIdx.x >> 5;
    #pragma unroll
    for (int j = 0; j < 4; j++) {
        int tok = ry + 8 * j;
        tile[tok][tx] = g_Vbf[(size_t)(t0 + tok) * BERT + d0 + tx];
    }
    __syncthreads();
    #pragma unroll
    for (int j = 0; j < 4; j++) {
        int d = ry + 8 * j;
        g_Vt[(size_t)(d0 + d) * NPNT + t0 + tx] = tile[tx][d];
    }
}

// ---------------------------------------------------------------------------
// bf16 HMMA projection GEMM.  Round 16: min 2 blocks/SM (reg cap 128).
// ---------------------------------------------------------------------------
#define PK 32
#define PST 40

template<int DST, bool PERM>
__global__ __launch_bounds__(256, 2)
void gemm_bias_mma_kernel(const float* __restrict__ A, const float* __restrict__ W,
                          const float* __restrict__ bias, int M, int N, int K) {
    __nv_bfloat16* C = (DST == 0) ? g_Qbf : (DST == 1) ? g_Kbf : g_Vbf;
    __shared__ __align__(16) __nv_bfloat16 As[128 * PST];
    __shared__ __align__(16) __nv_bfloat16 Ws[64 * PST];

    const int tid  = threadIdx.x;
    const int lane = tid & 31;
    const int w    = tid >> 5;
    const int g    = lane >> 2, t = lane & 3;
    const int wr   = w & 3, wc = w >> 2;
    const int m0   = blockIdx.y * 128, n0 = blockIdx.x * 64;

    float acc[2][4][4];
    #pragma unroll
    for (int mi = 0; mi < 2; mi++)
        #pragma unroll
        for (int ni = 0; ni < 4; ni++)
            #pragma unroll
            for (int q = 0; q < 4; q++) acc[mi][ni][q] = 0.f;

    for (int k0 = 0; k0 < K; k0 += PK) {
        #pragma unroll
        for (int i = 0; i < 16; i++) {
            int idx = tid + i * 256;
            int m = idx >> 5, k = idx & 31;
            As[m * PST + k] = __float2bfloat16(A[(size_t)(m0 + m) * K + k0 + k]);
        }
        #pragma unroll
        for (int i = 0; i < 8; i++) {
            int idx = tid + i * 256;
            int k = idx >> 6, n = idx & 63;
            Ws[n * PST + k] = __float2bfloat16(W[(size_t)(k0 + k) * N + n0 + n]);
        }
        __syncthreads();

        #pragma unroll
        for (int kf = 0; kf < 2; kf++) {
            uint32_t a[2][4], b[4][2];
            #pragma unroll
            for (int mi = 0; mi < 2; mi++) {
                const __nv_bfloat16* base = As + (wr * 32 + mi * 16 + g) * PST + kf * 16 + 2 * t;
                a[mi][0] = *(const uint32_t*)(base);
                a[mi][1] = *(const uint32_t*)(base + 8 * PST);
                a[mi][2] = *(const uint32_t*)(base + 8);
                a[mi][3] = *(const uint32_t*)(base + 8 * PST + 8);
            }
            #pragma unroll
            for (int ni = 0; ni < 4; ni++) {
                const __nv_bfloat16* base = Ws + (wc * 32 + ni * 8 + g) * PST + kf * 16 + 2 * t;
                b[ni][0] = *(const uint32_t*)(base);
                b[ni][1] = *(const uint32_t*)(base + 8);
            }
            #pragma unroll
            for (int mi = 0; mi < 2; mi++)
                #pragma unroll
                for (int ni = 0; ni < 4; ni++)
                    mma16816(acc[mi][ni][0], acc[mi][ni][1], acc[mi][ni][2], acc[mi][ni][3],
                             a[mi][0], a[mi][1], a[mi][2], a[mi][3], b[ni][0], b[ni][1]);
        }
        __syncthreads();
    }

    #pragma unroll
    for (int mi = 0; mi < 2; mi++) {
        int row0 = m0 + wr * 32 + mi * 16 + g;
        #pragma unroll
        for (int ni = 0; ni < 4; ni++) {
            int ncol = n0 + wc * 32 + ni * 8 + 2 * t;
            #pragma unroll
            for (int q = 0; q < 4; q++) {
                int rr = row0 + (q >> 1) * 8;
                int nn = ncol + (q & 1);
                float v = acc[mi][ni][q] + bias[nn];
                int nc = PERM ? ((nn & 3) * 128 + (nn >> 2)) : nn;
                C[(size_t)rr * N + nc] = __float2bfloat16(v);
            }
        }
    }
}

// ---------------------------------------------------------------------------
// bf16 tensor-core attention.  Round 16: register-prefetch double buffering.
// ---------------------------------------------------------------------------
#define QT 64
#define KT 32

__global__ __launch_bounds__(256, 2)
void attn_mma_kernel(const int* __restrict__ batch_p,
                     const int* __restrict__ batch_h) {
    __shared__ __align__(16) __nv_bfloat16 Qs[QT * 136];
    __shared__ __align__(16) __nv_bfloat16 Ks[KT * 136];
    __shared__ __align__(16) __nv_bfloat16 Vt[192 * 40];
    __shared__ __align__(16) __nv_bfloat16 Ps[QT * 48];
    __shared__ float denom[QT];
    __shared__ int   bpS[KT];

    const int h    = blockIdx.y;
    const int n0q  = blockIdx.x * QT;
    const int tid  = threadIdx.x;
    const int lane = tid & 31;
    const int w    = tid >> 5;
    const int g    = lane >> 2;
    const int t    = lane & 3;
    const int r    = w & 3;
    const int c    = w >> 2;

    for (int u = tid; u < QT * 64; u += 256) {
        int row = u >> 6, du = u & 63;
        *((uint32_t*)(Qs + row * 136) + du) =
            *((const uint32_t*)(g_Qbf + (size_t)(n0q + row) * DDIM + h * 128) + du);
    }
    if (tid < QT) denom[tid] = 0.f;

    const int bh0 = batch_h[n0q + 16 * r + g];
    const int bh1 = batch_h[n0q + 16 * r + g + 8];

    float acc[12][4];
    #pragma unroll
    for (int nf = 0; nf < 12; nf++)
        #pragma unroll
        for (int q = 0; q < 4; q++) acc[nf][q] = 0.f;

    const float scale = 0.08838834764831845f;

    // ---- register prefetch buffers (K: 8 words, V: 12 words, bp: 1) ----
    uint32_t kreg[8], vreg[12];
    int bpreg = 0;
    {
        const int m0 = 0;
        #pragma unroll
        for (int i = 0; i < 8; i++) {
            int u = tid + i * 256;
            int row = u >> 6, du = u & 63;
            kreg[i] = *((const uint32_t*)(g_Kbf + (size_t)(m0 + row) * DDIM + h * 128) + du);
        }
        #pragma unroll
        for (int i = 0; i < 12; i++) {
            int u = tid + i * 256;
            int row = u >> 4, du = u & 15;
            vreg[i] = *((const uint32_t*)(g_Vt + (size_t)(h * 192 + row) * NPNT + m0) + du);
        }
        if (tid < KT) bpreg = batch_p[m0 + tid];
    }

    for (int m0 = 0; m0 < NPNT; m0 += KT) {
        // ---- store prefetched tile to smem ----
        #pragma unroll
        for (int i = 0; i < 8; i++) {
            int u = tid + i * 256;
            int row = u >> 6, du = u & 63;
            *((uint32_t*)(Ks + row * 136) + du) = kreg[i];
        }
        #pragma unroll
        for (int i = 0; i < 12; i++) {
            int u = tid + i * 256;
            int row = u >> 4, du = u & 15;
            *((uint32_t*)(Vt + row * 40) + du) = vreg[i];
        }
        if (tid < KT) bpS[tid] = bpreg;
        __syncthreads();

        // ---- prefetch NEXT tile (latency overlapped with mma below) ----
        const int m1 = m0 + KT;
        if (m1 < NPNT) {
            #pragma unroll
            for (int i = 0; i < 8; i++) {
                int u = tid + i * 256;
                int row = u >> 6, du = u & 63;
                kreg[i] = *((const uint32_t*)(g_Kbf + (size_t)(m1 + row) * DDIM + h * 128) + du);
            }
            #pragma unroll
            for (int i = 0; i < 12; i++) {
                int u = tid + i * 256;
                int row = u >> 4, du = u & 15;
                vreg[i] = *((const uint32_t*)(g_Vt + (size_t)(h * 192 + row) * NPNT + m1) + du);
            }
            if (tid < KT) bpreg = batch_p[m1 + tid];
        }

        // ---- stage 1: dual accumulation chains ----
        float s[2][4], s2[2][4];
        #pragma unroll
        for (int nf = 0; nf < 2; nf++)
            #pragma unroll
            for (int q = 0; q < 4; q++) { s[nf][q] = 0.f; s2[nf][q] = 0.f; }

        const int qr = 16 * r, kc = 16 * c;
        #pragma unroll
        for (int kf = 0; kf < 8; kf++) {
            uint32_t a0 = *(const uint32_t*)(Qs + (qr + g)     * 136 + 16 * kf + 2 * t);
            uint32_t a1 = *(const uint32_t*)(Qs + (qr + g + 8) * 136 + 16 * kf + 2 * t);
            uint32_t a2 = *(const uint32_t*)(Qs + (qr + g)     * 136 + 16 * kf + 2 * t + 8);
            uint32_t a3 = *(const uint32_t*)(Qs + (qr + g + 8) * 136 + 16 * kf + 2 * t + 8);
            #pragma unroll
            for (int nf = 0; nf < 2; nf++) {
                uint32_t b0 = *(const uint32_t*)(Ks + (kc + 8 * nf + g) * 136 + 16 * kf + 2 * t);
                uint32_t b1 = *(const uint32_t*)(Ks + (kc + 8 * nf + g) * 136 + 16 * kf + 2 * t + 8);
                if (kf & 1)
                    mma16816(s2[nf][0], s2[nf][1], s2[nf][2], s2[nf][3], a0, a1, a2, a3, b0, b1);
                else
                    mma16816(s[nf][0],  s[nf][1],  s[nf][2],  s[nf][3],  a0, a1, a2, a3, b0, b1);
            }
        }

        float rs0 = 0.f, rs1 = 0.f;
        #pragma unroll
        for (int nf = 0; nf < 2; nf++) {
            int col = kc + 8 * nf + 2 * t;
            int bpa = bpS[col], bpb = bpS[col + 1];
            float e00 = (bh0 == bpa) ? 0.f : __expf((s[nf][0] + s2[nf][0]) * scale);
            float e01 = (bh0 == bpb) ? 0.f : __expf((s[nf][1] + s2[nf][1]) * scale);
            float e10 = (bh1 == bpa) ? 0.f : __expf((s[nf][2] + s2[nf][2]) * scale);
            float e11 = (bh1 == bpb) ? 0.f : __expf((s[nf][3] + s2[nf][3]) * scale);
            rs0 += e00 + e01;
            rs1 += e10 + e11;
            *(uint32_t*)(Ps + (qr + g)     * 48 + col) = packbf(e00, e01);
            *(uint32_t*)(Ps + (qr + g + 8) * 48 + col) = packbf(e10, e11);
        }
        rs0 += __shfl_xor_sync(0xffffffffu, rs0, 1);
        rs0 += __shfl_xor_sync(0xffffffffu, rs0, 2);
        rs1 += __shfl_xor_sync(0xffffffffu, rs1, 1);
        rs1 += __shfl_xor_sync(0xffffffffu, rs1, 2);
        if (t == 0) {
            atomicAdd(&denom[qr + g],     rs0);
            atomicAdd(&denom[qr + g + 8], rs1);
        }
        __syncthreads();

        // ---- stage 2: attended += P @ V ----
        {
            const int e0 = 96 * c;
            #pragma unroll
            for (int kf = 0; kf < 2; kf++) {
                uint32_t a0 = *(const uint32_t*)(Ps + (qr + g)     * 48 + 16 * kf + 2 * t);
                uint32_t a1 = *(const uint32_t*)(Ps + (qr + g + 8) * 48 + 16 * kf + 2 * t);
                uint32_t a2 = *(const uint32_t*)(Ps + (qr + g)     * 48 + 16 * kf + 2 * t + 8);
                uint32_t a3 = *(const uint32_t*)(Ps + (qr + g + 8) * 48 + 16 * kf + 2 * t + 8);
                #pragma unroll
                for (int nf = 0; nf < 12; nf++) {
                    uint32_t b0 = *(const uint32_t*)(Vt + (e0 + 8 * nf + g) * 40 + 16 * kf + 2 * t);
                    uint32_t b1 = *(const uint32_t*)(Vt + (e0 + 8 * nf + g) * 40 + 16 * kf + 2 * t + 8);
                    mma16816(acc[nf][0], acc[nf][1], acc[nf][2], acc[nf][3],
                             a0, a1, a2, a3, b0, b1);
                }
            }
        }
        __syncthreads();
    }

    const float inv0 = 1.0f / denom[16 * r + g];
    const float inv1 = 1.0f / denom[16 * r + g + 8];
    const int row0 = n0q + 16 * r + g;
    const int row1 = row0 + 8;
    #pragma unroll
    for (int nf = 0; nf < 12; nf++) {
        int col = h * 192 + 96 * c + 8 * nf + 2 * t;
        float2 v0 = make_float2(acc[nf][0] * inv0, acc[nf][1] * inv0);
        float2 v1 = make_float2(acc[nf][2] * inv1, acc[nf][3] * inv1);
        *(float2*)(g_att + (size_t)row0 * BERT + col) = v0;
        *(float2*)(g_att + (size_t)row1 * BERT + col) = v1;
    }
}

// ---------------------------------------------------------------------------
// h1 = gelu(concat(ctx_h, lhs_h - att) @ W1 + b1)   (fp32)
// ---------------------------------------------------------------------------
#define GM_TM 128
#define GM_TN 64
#define GM_TK 16

__global__ __launch_bounds__(256)
void gemm_feats_kernel(const float* __restrict__ ctx_h, const float* __restrict__ lhs_h,
                       const float* __restrict__ W1, const float* __restrict__ b1) {
    const int N = 256, K = DDIM + BERT;
    __shared__ float As[GM_TK][GM_TM + 1];
    __shared__ float Bs[GM_TK][GM_TN];
    int tid = threadIdx.x;
    int m0 = blockIdx.y * GM_TM, n0 = blockIdx.x * GM_TN;
    int tx = tid & 15, ty = tid >> 4;
    float acc[8][4];
    #pragma unroll
    for (int i = 0; i < 8; i++)
        #pragma unroll
        for (int j = 0; j < 4; j++) acc[i][j] = 0.f;

    for (int k0 = 0; k0 < K; k0 += GM_TK) {
        #pragma unroll
        for (int i = 0; i < 8; i++) {
            int idx = tid + i * 256;
            int m = idx >> 4, k = idx & 15;
            int gm = m0 + m, gk = k0 + k;
            float a;
            if (gk < DDIM) a = ctx_h[(size_t)gm * DDIM + gk];
            else {
                int kk = gk - DDIM;
                a = lhs_h[(size_t)gm * BERT + kk] - g_att[(size_t)gm * BERT + kk];
            }
            As[k][m] = a;
        }
        #pragma unroll
        for (int i = 0; i < 4; i++) {
            int idx = tid + i * 256;
            int k = idx >> 6, n = idx & 63;
            Bs[k][n] = W1[(size_t)(k0 + k) * N + (n0 + n)];
        }
        __syncthreads();
        #pragma unroll
        for (int k = 0; k < GM_TK; k++) {
            float a[8], b[4];
            #pragma unroll
            for (int i = 0; i < 8; i++) a[i] = As[k][ty * 8 + i];
            #pragma unroll
            for (int j = 0; j < 4; j++) b[j] = Bs[k][tx * 4 + j];
            #pragma unroll
            for (int i = 0; i < 8; i++)
                #pragma unroll
                for (int j = 0; j < 4; j++) acc[i][j] += a[i] * b[j];
        }
        __syncthreads();
    }
    #pragma unroll
    for (int i = 0; i < 8; i++) {
        int m = m0 + ty * 8 + i;
        #pragma unroll
        for (int j = 0; j < 4; j++) {
            int n = n0 + tx * 4 + j;
            float x = acc[i][j] + b1[n];
            g_h1[(size_t)m * 256 + n] = x * normcdff(x);
        }
    }
}

// ---------------------------------------------------------------------------
// h2 = h1@W2 ; LayerNorm(128) ; atomic pool.
// ---------------------------------------------------------------------------
__global__ __launch_bounds__(128)
void h2_ln_pool_kernel(const float* __restrict__ W2, const float* __restrict__ ln_g,
                       const float* __restrict__ ln_b, const int* __restrict__ batch_h) {
    int n = blockIdx.x;
    int c = threadIdx.x;
    __shared__ float h1s[256];
    __shared__ float red[4];
    h1s[c]       = g_h1[n * 256 + c];
    h1s[c + 128] = g_h1[n * 256 + 128 + c];
    __syncthreads();
    float acc = 0.f;
    #pragma unroll 8
    for (int k = 0; k < 256; k++) acc += h1s[k] * W2[k * 128 + c];

    float s = acc;
    #pragma unroll
    for (int o = 16; o > 0; o >>= 1) s += __shfl_xor_sync(0xffffffffu, s, o);
    if ((c & 31) == 0) red[c >> 5] = s;
    __syncthreads();
    float mu = (red[0] + red[1] + red[2] + red[3]) * (1.f / 128.f);
    __syncthreads();
    float d = acc - mu;
    float v = d * d;
    #pragma unroll
    for (int o = 16; o > 0; o >>= 1) v += __shfl_xor_sync(0xffffffffu, v, o);
    if ((c & 31) == 0) red[c >> 5] = v;
    __syncthreads();
    float var = (red[0] + red[1] + red[2] + red[3]) * (1.f / 128.f);
    float y = d * rsqrtf(var + 1e-5f) * ln_g[c] + ln_b[c];
    int b = batch_h[n];
    atomicAdd(&g_pooled[b * 128 + c], y);
    if (c == 0) atomicAdd(&g_cnt[b], 1.0f);
}

__global__ void final_kernel(const float* __restrict__ Wc, const float* __restrict__ bc,
                             float* __restrict__ out) {
    int t = threadIdx.x;
    if (t < NB * 3) {
        int b = t / 3, c = t % 3;
        float inv = 1.0f / fmaxf(g_cnt[b], 1.0f);
        float acc = 0.f;
        #pragma unroll 4
        for (int k = 0; k < 128; k++) acc += g_pooled[b * 128 + k] * Wc[k * 3 + c];
        out[b * 3 + c] = acc * inv + bc[c];
    }
}

// ---------------------------------------------------------------------------
extern "C" void kernel_launch(void* const* d_in, const int* in_sizes, int n_in,
                              void* d_out, int out_size) {
    const float* ctx_p   = (const float*)d_in[0];
    const float* ctx_h   = (const float*)d_in[1];
    const float* lhs_p   = (const float*)d_in[2];
    const float* lhs_h   = (const float*)d_in[3];
    const int*   batch_p = (const int*)d_in[4];   // int32 (JAX x64 disabled)
    const int*   batch_h = (const int*)d_in[5];
    const float* Wq = (const float*)d_in[6];
    const float* bq = (const float*)d_in[7];
    const float* Wk = (const float*)d_in[8];
    const float* bk = (const float*)d_in[9];
    const float* Wv = (const float*)d_in[10];
    const float* bv = (const float*)d_in[11];
    const float* W1 = (const float*)d_in[12];
    const float* b1 = (const float*)d_in[13];
    const float* W2 = (const float*)d_in[14];
    const float* ln_g = (const float*)d_in[15];
    const float* ln_b = (const float*)d_in[16];
    const float* Wc = (const float*)d_in[17];
    const float* bc = (const float*)d_in[18];
    float* out = (float*)d_out;

    zero_pool_kernel<<<16, 256>>>();

    gemm_bias_mma_kernel<0, true ><<<dim3(DDIM / 64, NHNT / 128), 256>>>(
        ctx_h, Wq, bq, NHNT, DDIM, DDIM);
    gemm_bias_mma_kernel<1, true ><<<dim3(DDIM / 64, NPNT / 128), 256>>>(
        ctx_p, Wk, bk, NPNT, DDIM, DDIM);
    gemm_bias_mma_kernel<2, false><<<dim3(BERT / 64, NPNT / 128), 256>>>(
        lhs_p, Wv, bv, NPNT, BERT, BERT);

    transpose_v_kernel<<<dim3(NPNT / 32, BERT / 32), 256>>>();

    attn_mma_kernel<<<dim3(NHNT / QT, HEADS), 256>>>(batch_p, batch_h);

    gemm_feats_kernel<<<dim3(256 / GM_TN, NHNT / GM_TM), 256>>>(ctx_h, lhs_h, W1, b1);

    h2_ln_pool_kernel<<<NHNT, 128>>>(W2, ln_g, ln_b, batch_h);

    final_kernel<<<1, 96>>>(Wc, bc, out);
}